// round 9
// baseline (speedup 1.0000x reference)
#include <cuda_runtime.h>
#include <cstdint>

// Problem constants (fixed-shape problem)
#define B_  4
#define S_  2048
#define D_  1024
#define H_  16
#define DH_ 64
#define M_  (B_ * S_)   // 8192 rows for all projections

typedef unsigned long long ull;

// ---------------------------------------------------------------------------
// Packed f32x2 helpers (SASS FFMA2 — 2 fp32 FMAs per instruction, rt_SMSP=2)
// ---------------------------------------------------------------------------
__device__ __forceinline__ ull pack2(float lo, float hi) {
    ull r;
    asm("mov.b64 %0, {%1, %2};" : "=l"(r) : "f"(lo), "f"(hi));
    return r;
}
__device__ __forceinline__ void unpack2(ull v, float& lo, float& hi) {
    asm("mov.b64 {%0, %1}, %2;" : "=f"(lo), "=f"(hi) : "l"(v));
}
__device__ __forceinline__ ull fma2(ull a, ull b, ull c) {
    ull d;
    asm("fma.rn.f32x2 %0, %1, %2, %3;" : "=l"(d) : "l"(a), "l"(b), "l"(c));
    return d;
}

// ---------------------------------------------------------------------------
// Scratch (device globals: allocation-free, graph-capturable)
// q,k,v in [B,H,S,Dh]; o_concat in [B,S,D]
// ---------------------------------------------------------------------------
__device__ float g_q[B_ * H_ * S_ * DH_];
__device__ float g_k[B_ * H_ * S_ * DH_];
__device__ float g_v[B_ * H_ * S_ * DH_];
__device__ float g_o[B_ * S_ * D_];

// ---------------------------------------------------------------------------
// GEMM (NT): C[M,N] = A[M,K] * W[N,K]^T + bias[N]
// MODE 0: C row-major [M,N]
// MODE 1: scatter to [B,H,S,Dh]  (row = b*S+s, col = h*64+dh)
// 128x128 block, BK=8, 256 threads, 8x8 microtile, packed f32x2 math.
// B-operand lane pairs (j, j+1) are contiguous in smem -> loaded directly as
// ulonglong2 (no packing); A-operand broadcast-packed (8 packs / k-step).
// ---------------------------------------------------------------------------
template <int MODE>
__global__ __launch_bounds__(256) void gemm_nt(
    const float* __restrict__ A, const float* __restrict__ W,
    const float* __restrict__ bias, float* __restrict__ C,
    int M, int N, int K)
{
    __shared__ __align__(16) float As[8][128];  // transposed: As[k][m]
    __shared__ __align__(16) float Ws[8][128];  // transposed: Ws[k][n]

    const int tid = threadIdx.x;
    const int tx = tid & 15;       // 0..15
    const int ty = tid >> 4;       // 0..15
    const int bm = blockIdx.y * 128;
    const int bn = blockIdx.x * 128;

    const int lr = tid >> 1;            // 0..127 (row within tile)
    const int lc = (tid & 1) * 4;       // 0 or 4 (k offset within BK)
    const float* Ap = A + (size_t)(bm + lr) * K + lc;
    const float* Wp = W + (size_t)(bn + lr) * K + lc;

    ull acc[8][4];
#pragma unroll
    for (int i = 0; i < 8; i++)
#pragma unroll
        for (int jj = 0; jj < 4; jj++) acc[i][jj] = 0ULL;

    float4 av = *(const float4*)Ap;
    float4 wv = *(const float4*)Wp;

    for (int k0 = 0; k0 < K; k0 += 8) {
        As[lc + 0][lr] = av.x; As[lc + 1][lr] = av.y;
        As[lc + 2][lr] = av.z; As[lc + 3][lr] = av.w;
        Ws[lc + 0][lr] = wv.x; Ws[lc + 1][lr] = wv.y;
        Ws[lc + 2][lr] = wv.z; Ws[lc + 3][lr] = wv.w;
        __syncthreads();

        if (k0 + 8 < K) {
            av = *(const float4*)(Ap + k0 + 8);
            wv = *(const float4*)(Wp + k0 + 8);
        }

#pragma unroll
        for (int k = 0; k < 8; k++) {
            float a[8];
            *(float4*)(a)     = *(const float4*)&As[k][ty * 8];
            *(float4*)(a + 4) = *(const float4*)&As[k][ty * 8 + 4];
            const ulonglong2 b01 = *(const ulonglong2*)&Ws[k][tx * 8];
            const ulonglong2 b23 = *(const ulonglong2*)&Ws[k][tx * 8 + 4];
            ull b2[4];
            b2[0] = b01.x; b2[1] = b01.y; b2[2] = b23.x; b2[3] = b23.y;
#pragma unroll
            for (int i = 0; i < 8; i++) {
                const ull a2 = pack2(a[i], a[i]);
#pragma unroll
                for (int jj = 0; jj < 4; jj++)
                    acc[i][jj] = fma2(a2, b2[jj], acc[i][jj]);
            }
        }
        __syncthreads();
    }

    // epilogue
#pragma unroll
    for (int i = 0; i < 8; i++) {
        const int row = bm + ty * 8 + i;
#pragma unroll
        for (int jj = 0; jj < 4; jj++) {
            float v0, v1;
            unpack2(acc[i][jj], v0, v1);
            const int col0 = bn + tx * 8 + 2 * jj;
            const float r0 = v0 + bias[col0];
            const float r1 = v1 + bias[col0 + 1];
            if (MODE == 0) {
                C[(size_t)row * N + col0]     = r0;
                C[(size_t)row * N + col0 + 1] = r1;
            } else {
                const int bb = row >> 11;          // row / S_
                const int ss = row & (S_ - 1);
                const int h  = col0 >> 6;          // col / DH_ (pair never crosses a head: col0 even)
                const int dh = col0 & (DH_ - 1);
                float* dst = &((float*)0)[0];      // silence unused warn pattern
                (void)dst;
                float* base = (float*)C + (((size_t)(bb * H_ + h)) * S_ + ss) * DH_ + dh;
                base[0] = r0;
                base[1] = r1;
            }
        }
    }
}

// ---------------------------------------------------------------------------
// Sigmoid attention, per (b,h): O = sigmoid(Q K^T / 8) V    (packed f32x2)
// Q tile 128 rows; KV tile 128 rows; Dh = 64; 256 threads.
// Stage 1: rows ty+16i (lanes = i-pairs), cols tx+16j.
// Stage 2: rows ty+16i (lanes = i-pairs), cols tx*4+j (contiguous dh -> V via
//          one LDS.128, coalesced float4 output stores).
// Pads: Qs/Ks stride 65, Vs stride 64, Ps stride 129 (bank-conflict-free).
// ---------------------------------------------------------------------------
__global__ __launch_bounds__(256) void attn_kernel(
    const float* __restrict__ Qg, const float* __restrict__ Kg,
    const float* __restrict__ Vg, float* __restrict__ Og)
{
    extern __shared__ float sm[];
    float* Qs = sm;                    // [128][65]
    float* Ks = Qs + 128 * 65;         // [128][65]
    float* Vs = Ks + 128 * 65;         // [128][64]
    float* Ps = Vs + 128 * 64;         // [128][129]

    const int tid = threadIdx.x;
    const int tx = tid & 15;
    const int ty = tid >> 4;
    const int bh = blockIdx.y;             // 0..63  (b*H + h)
    const int q0 = blockIdx.x * 128;

    const float* Qp = Qg + (size_t)bh * S_ * DH_;
    const float* Kp = Kg + (size_t)bh * S_ * DH_;
    const float* Vp = Vg + (size_t)bh * S_ * DH_;

    // load Q tile [128,64] once (padded stride 65)
#pragma unroll
    for (int it = 0; it < 8; it++) {
        const int f = tid + it * 256;
        const int r = f >> 4;
        const int c = (f & 15) << 2;
        const float4 qv = *(const float4*)(Qp + (size_t)(q0 + r) * DH_ + c);
        float* qd = &Qs[r * 65 + c];
        qd[0] = qv.x; qd[1] = qv.y; qd[2] = qv.z; qd[3] = qv.w;
    }

    ull o2[4][4];   // lanes = i-pair (rows ty+16*(2ii), ty+16*(2ii+1)); cols tx*4+j
#pragma unroll
    for (int ii = 0; ii < 4; ii++)
#pragma unroll
        for (int j = 0; j < 4; j++) o2[ii][j] = 0ULL;

    for (int j0 = 0; j0 < S_; j0 += 128) {
        __syncthreads();  // prev iter's Ps/Vs reads complete before overwrite

        // load K (stride 65) and V (stride 64) tiles
#pragma unroll
        for (int it = 0; it < 8; it++) {
            const int f = tid + it * 256;
            const int r = f >> 4;
            const int c = (f & 15) << 2;
            const float4 kv = *(const float4*)(Kp + (size_t)(j0 + r) * DH_ + c);
            float* kd = &Ks[r * 65 + c];
            kd[0] = kv.x; kd[1] = kv.y; kd[2] = kv.z; kd[3] = kv.w;
            *(float4*)&Vs[r * 64 + c] =
                *(const float4*)(Vp + (size_t)(j0 + r) * DH_ + c);
        }
        __syncthreads();

        // Stage 1: S[128q x 128kv] = Q * K^T, lanes over i-pairs
        ull s2[4][8];
#pragma unroll
        for (int ii = 0; ii < 4; ii++)
#pragma unroll
            for (int j = 0; j < 8; j++) s2[ii][j] = 0ULL;

#pragma unroll 8
        for (int k = 0; k < DH_; k++) {
            float a[8], b[8];
#pragma unroll
            for (int i = 0; i < 8; i++) a[i] = Qs[(ty + 16 * i) * 65 + k];
#pragma unroll
            for (int j = 0; j < 8; j++) b[j] = Ks[(tx + 16 * j) * 65 + k];
            ull a2[4];
#pragma unroll
            for (int ii = 0; ii < 4; ii++) a2[ii] = pack2(a[2 * ii], a[2 * ii + 1]);
#pragma unroll
            for (int j = 0; j < 8; j++) {
                const ull b2 = pack2(b[j], b[j]);
#pragma unroll
                for (int ii = 0; ii < 4; ii++)
                    s2[ii][j] = fma2(a2[ii], b2, s2[ii][j]);
            }
        }

        // sigmoid(s/8) -> Ps (stride 129)
#pragma unroll
        for (int ii = 0; ii < 4; ii++) {
            const int r0 = (ty + 16 * (2 * ii)) * 129;
            const int r1 = (ty + 16 * (2 * ii + 1)) * 129;
#pragma unroll
            for (int j = 0; j < 8; j++) {
                float x0, x1;
                unpack2(s2[ii][j], x0, x1);
                const int col = tx + 16 * j;
                Ps[r0 + col] = __fdividef(1.0f, 1.0f + __expf(-x0 * 0.125f));
                Ps[r1 + col] = __fdividef(1.0f, 1.0f + __expf(-x1 * 0.125f));
            }
        }
        __syncthreads();

        // Stage 2: O[128q x 64dh] += P * V, lanes over i-pairs, cols tx*4+j
#pragma unroll 8
        for (int k = 0; k < 128; k++) {
            float p[8];
#pragma unroll
            for (int i = 0; i < 8; i++) p[i] = Ps[(ty + 16 * i) * 129 + k];
            ull p2[4];
#pragma unroll
            for (int ii = 0; ii < 4; ii++) p2[ii] = pack2(p[2 * ii], p[2 * ii + 1]);
            const float4 vvv = *(const float4*)&Vs[k * 64 + tx * 4];
            const float vv[4] = {vvv.x, vvv.y, vvv.z, vvv.w};
#pragma unroll
            for (int j = 0; j < 4; j++) {
                const ull v2 = pack2(vv[j], vv[j]);
#pragma unroll
                for (int ii = 0; ii < 4; ii++)
                    o2[ii][j] = fma2(p2[ii], v2, o2[ii][j]);
            }
        }
    }

    // write O to concat layout [B,S,D]: o_concat[b][s][h*64 + tx*4 + j]
    const int bb = bh >> 4;
    const int h  = bh & (H_ - 1);
#pragma unroll
    for (int ii = 0; ii < 4; ii++) {
        float lo[4], hi[4];
#pragma unroll
        for (int j = 0; j < 4; j++) unpack2(o2[ii][j], lo[j], hi[j]);
        const int s0 = q0 + ty + 16 * (2 * ii);
        const int s1 = q0 + ty + 16 * (2 * ii + 1);
        float4 w0 = make_float4(lo[0], lo[1], lo[2], lo[3]);
        float4 w1 = make_float4(hi[0], hi[1], hi[2], hi[3]);
        *(float4*)&Og[((size_t)bb * S_ + s0) * D_ + h * DH_ + tx * 4] = w0;
        *(float4*)&Og[((size_t)bb * S_ + s1) * D_ + h * DH_ + tx * 4] = w1;
    }
}

// ---------------------------------------------------------------------------
// Launcher
// ---------------------------------------------------------------------------
extern "C" void kernel_launch(void* const* d_in, const int* in_sizes, int n_in,
                              void* d_out, int out_size)
{
    const float* q  = (const float*)d_in[0];
    const float* k  = (const float*)d_in[1];
    const float* v  = (const float*)d_in[2];
    const float* Wq = (const float*)d_in[3];
    const float* bq = (const float*)d_in[4];
    const float* Wk = (const float*)d_in[5];
    const float* bk = (const float*)d_in[6];
    const float* Wv = (const float*)d_in[7];
    const float* bv = (const float*)d_in[8];
    const float* Wo = (const float*)d_in[9];
    const float* bo = (const float*)d_in[10];
    float* out = (float*)d_out;

    float *gq, *gk, *gv, *go;
    cudaGetSymbolAddress((void**)&gq, g_q);
    cudaGetSymbolAddress((void**)&gk, g_k);
    cudaGetSymbolAddress((void**)&gv, g_v);
    cudaGetSymbolAddress((void**)&go, g_o);

    const dim3 gg(D_ / 128, M_ / 128);  // (8, 64)

    gemm_nt<1><<<gg, 256>>>(q, Wq, bq, gq, M_, D_, D_);
    gemm_nt<1><<<gg, 256>>>(k, Wk, bk, gk, M_, D_, D_);
    gemm_nt<1><<<gg, 256>>>(v, Wv, bv, gv, M_, D_, D_);

    const int attn_smem =
        (128 * 65 + 128 * 65 + 128 * 64 + 128 * 129) * (int)sizeof(float);
    cudaFuncSetAttribute(attn_kernel, cudaFuncAttributeMaxDynamicSharedMemorySize, attn_smem);
    attn_kernel<<<dim3(S_ / 128, B_ * H_), 256, attn_smem>>>(gq, gk, gv, go);

    gemm_nt<0><<<gg, 256>>>(go, Wo, bo, out, M_, D_, D_);
}

// round 10
// speedup vs baseline: 2.4026x; 2.4026x over previous
#include <cuda_runtime.h>
#include <cuda_bf16.h>
#include <cstdint>

// Problem constants (fixed-shape problem)
#define B_  4
#define S_  2048
#define D_  1024
#define H_  16
#define DH_ 64
#define M_  (B_ * S_)   // 8192 rows for all projections

// ---------------------------------------------------------------------------
// Scratch (device globals: allocation-free, graph-capturable)
// ---------------------------------------------------------------------------
__device__ float g_q[B_ * H_ * S_ * DH_];
__device__ float g_k[B_ * H_ * S_ * DH_];
__device__ float g_v[B_ * H_ * S_ * DH_];
__device__ float g_o[B_ * S_ * D_];

// ---------------------------------------------------------------------------
// MMA helpers (bf16 HMMA, m16n8k16, fp32 accumulate)
// ---------------------------------------------------------------------------
__device__ __forceinline__ uint32_t smem_u32(const void* p) {
    return (uint32_t)__cvta_generic_to_shared(p);
}

__device__ __forceinline__ void ldsm_x4(uint32_t& r0, uint32_t& r1,
                                        uint32_t& r2, uint32_t& r3, uint32_t a) {
    asm volatile("ldmatrix.sync.aligned.m8n8.x4.shared.b16 {%0,%1,%2,%3}, [%4];"
                 : "=r"(r0), "=r"(r1), "=r"(r2), "=r"(r3) : "r"(a));
}
__device__ __forceinline__ void ldsm_x4t(uint32_t& r0, uint32_t& r1,
                                         uint32_t& r2, uint32_t& r3, uint32_t a) {
    asm volatile("ldmatrix.sync.aligned.m8n8.x4.trans.shared.b16 {%0,%1,%2,%3}, [%4];"
                 : "=r"(r0), "=r"(r1), "=r"(r2), "=r"(r3) : "r"(a));
}
__device__ __forceinline__ void mma_bf16(float* d, const uint32_t* a, const uint32_t* b) {
    asm volatile(
        "mma.sync.aligned.m16n8k16.row.col.f32.bf16.bf16.f32 "
        "{%0,%1,%2,%3}, {%4,%5,%6,%7}, {%8,%9}, {%0,%1,%2,%3};"
        : "+f"(d[0]), "+f"(d[1]), "+f"(d[2]), "+f"(d[3])
        : "r"(a[0]), "r"(a[1]), "r"(a[2]), "r"(a[3]), "r"(b[0]), "r"(b[1]));
}

// Split two fp32 into packed bf16 hi-pair and lo-pair (x in low half).
__device__ __forceinline__ void split2(float x, float y, uint32_t& hi, uint32_t& lo) {
    __nv_bfloat16 xh = __float2bfloat16(x);
    __nv_bfloat16 yh = __float2bfloat16(y);
    __nv_bfloat16 xl = __float2bfloat16(x - __bfloat162float(xh));
    __nv_bfloat16 yl = __float2bfloat16(y - __bfloat162float(yh));
    __nv_bfloat162 h2 = __halves2bfloat162(xh, yh);
    __nv_bfloat162 l2 = __halves2bfloat162(xl, yl);
    hi = *(uint32_t*)&h2;
    lo = *(uint32_t*)&l2;
}

// ---------------------------------------------------------------------------
// GEMM (NT): C[M,N] = A[M,K] * W[N,K]^T + bias[N]   (bf16x3 tensor path)
// MODE 0: C row-major [M,N]; MODE 1: scatter to [B,H,S,Dh]
// CTA 128x128, BK=32, 256 threads (8 warps, 2x4). fp32 gmem -> hi/lo bf16 smem.
// ---------------------------------------------------------------------------
#define AST 40   // smem K-stride (32 + 8 pad) in bf16 elems

template <int MODE>
__global__ __launch_bounds__(256) void gemm_mma(
    const float* __restrict__ A, const float* __restrict__ W,
    const float* __restrict__ bias, float* __restrict__ C,
    int M, int N, int K)
{
    __shared__ __align__(16) __nv_bfloat16 sAh[128 * AST];
    __shared__ __align__(16) __nv_bfloat16 sAl[128 * AST];
    __shared__ __align__(16) __nv_bfloat16 sWh[128 * AST];
    __shared__ __align__(16) __nv_bfloat16 sWl[128 * AST];

    const int tid  = threadIdx.x;
    const int lane = tid & 31;
    const int wid  = tid >> 5;
    const int wm   = (wid >> 2) * 64;   // warp M offset (0,64)
    const int wn   = (wid & 3) * 32;    // warp N offset (0..96)
    const int bm   = blockIdx.y * 128;
    const int bn   = blockIdx.x * 128;

    // gmem staging map: 4 float4 per thread per operand
    int srow[4], sc4[4];
#pragma unroll
    for (int i = 0; i < 4; i++) {
        const int idx = tid + i * 256;
        srow[i] = idx >> 3;
        sc4[i]  = (idx & 7) * 4;
    }

    float4 av[4], wv[4];
#pragma unroll
    for (int i = 0; i < 4; i++) {
        av[i] = *(const float4*)(A + (size_t)(bm + srow[i]) * K + sc4[i]);
        wv[i] = *(const float4*)(W + (size_t)(bn + srow[i]) * K + sc4[i]);
    }

    float acc[4][4][4];
#pragma unroll
    for (int mt = 0; mt < 4; mt++)
#pragma unroll
        for (int nt = 0; nt < 4; nt++)
#pragma unroll
            for (int r = 0; r < 4; r++) acc[mt][nt][r] = 0.0f;

    // ldmatrix source addresses (element offsets precomputed per lane)
    const int a_r = lane & 15;          // row within 16
    const int a_k = (lane >> 4) * 8;    // k offset 0/8
    const int b_r = (lane & 7) + ((lane >> 4) & 1) * 8;  // n within 16
    const int b_k = ((lane >> 3) & 1) * 8;               // k offset 0/8

    for (int k0 = 0; k0 < K; k0 += 32) {
        // stage current chunk into smem (split fp32 -> bf16 hi/lo)
#pragma unroll
        for (int i = 0; i < 4; i++) {
            const int off = srow[i] * AST + sc4[i];
            uint32_t h, l;
            split2(av[i].x, av[i].y, h, l);
            *(uint32_t*)&sAh[off] = h; *(uint32_t*)&sAl[off] = l;
            split2(av[i].z, av[i].w, h, l);
            *(uint32_t*)&sAh[off + 2] = h; *(uint32_t*)&sAl[off + 2] = l;
            split2(wv[i].x, wv[i].y, h, l);
            *(uint32_t*)&sWh[off] = h; *(uint32_t*)&sWl[off] = l;
            split2(wv[i].z, wv[i].w, h, l);
            *(uint32_t*)&sWh[off + 2] = h; *(uint32_t*)&sWl[off + 2] = l;
        }
        __syncthreads();

        if (k0 + 32 < K) {
#pragma unroll
            for (int i = 0; i < 4; i++) {
                av[i] = *(const float4*)(A + (size_t)(bm + srow[i]) * K + k0 + 32 + sc4[i]);
                wv[i] = *(const float4*)(W + (size_t)(bn + srow[i]) * K + k0 + 32 + sc4[i]);
            }
        }

#pragma unroll
        for (int ks = 0; ks < 2; ks++) {
            uint32_t Ah[4][4], Al[4][4], Bh[4][2], Bl[4][2];
#pragma unroll
            for (int mt = 0; mt < 4; mt++) {
                const int eo = (wm + mt * 16 + a_r) * AST + ks * 16 + a_k;
                ldsm_x4(Ah[mt][0], Ah[mt][1], Ah[mt][2], Ah[mt][3], smem_u32(&sAh[eo]));
                ldsm_x4(Al[mt][0], Al[mt][1], Al[mt][2], Al[mt][3], smem_u32(&sAl[eo]));
            }
#pragma unroll
            for (int p = 0; p < 2; p++) {
                const int eo = (wn + p * 16 + b_r) * AST + ks * 16 + b_k;
                ldsm_x4(Bh[2 * p][0], Bh[2 * p][1], Bh[2 * p + 1][0], Bh[2 * p + 1][1],
                        smem_u32(&sWh[eo]));
                ldsm_x4(Bl[2 * p][0], Bl[2 * p][1], Bl[2 * p + 1][0], Bl[2 * p + 1][1],
                        smem_u32(&sWl[eo]));
            }
#pragma unroll
            for (int mt = 0; mt < 4; mt++)
#pragma unroll
                for (int nt = 0; nt < 4; nt++) {
                    mma_bf16(acc[mt][nt], Ah[mt], Bh[nt]);
                    mma_bf16(acc[mt][nt], Ah[mt], Bl[nt]);
                    mma_bf16(acc[mt][nt], Al[mt], Bh[nt]);
                }
        }
        __syncthreads();
    }

    // epilogue from fragment layout
#pragma unroll
    for (int mt = 0; mt < 4; mt++) {
        const int r0 = bm + wm + mt * 16 + (lane >> 2);
#pragma unroll
        for (int nt = 0; nt < 4; nt++) {
            const int c0 = bn + wn + nt * 8 + (lane & 3) * 2;
            const float bz0 = bias[c0], bz1 = bias[c0 + 1];
#pragma unroll
            for (int half = 0; half < 2; half++) {
                const int row = r0 + half * 8;
                const float v0 = acc[mt][nt][2 * half]     + bz0;
                const float v1 = acc[mt][nt][2 * half + 1] + bz1;
                if (MODE == 0) {
                    C[(size_t)row * N + c0]     = v0;
                    C[(size_t)row * N + c0 + 1] = v1;
                } else {
                    const int bb = row >> 11;
                    const int ss = row & (S_ - 1);
                    const int h  = c0 >> 6;
                    const int dh = c0 & (DH_ - 1);
                    float* base = C + (((size_t)(bb * H_ + h)) * S_ + ss) * DH_ + dh;
                    base[0] = v0; base[1] = v1;
                }
            }
        }
    }
}

// ---------------------------------------------------------------------------
// Sigmoid attention (bf16x3 tensor path), per (b,h): O = sigmoid(QK^T/8) V
// Q tile 128, KV tile 128, Dh 64. 256 threads (8 warps, 2x4).
// smem: Q/K/V hi+lo [128][72] bf16, P hi+lo [128][136] bf16. 180224 B dynamic.
// ---------------------------------------------------------------------------
#define QST 72    // Q/K/V smem stride (64 + 8)
#define PST 136   // P smem stride (128 + 8)
#define OFF_QH 0
#define OFF_QL (128 * QST)
#define OFF_KH (2 * 128 * QST)
#define OFF_KL (3 * 128 * QST)
#define OFF_VH (4 * 128 * QST)
#define OFF_VL (5 * 128 * QST)
#define OFF_PH (6 * 128 * QST)
#define OFF_PL (6 * 128 * QST + 128 * PST)
#define ATTN_SMEM ((6 * 128 * QST + 2 * 128 * PST) * 2)

__global__ __launch_bounds__(256) void attn_mma(
    const float* __restrict__ Qg, const float* __restrict__ Kg,
    const float* __restrict__ Vg, float* __restrict__ Og)
{
    extern __shared__ __nv_bfloat16 sm[];
    __nv_bfloat16* Qh = sm + OFF_QH;
    __nv_bfloat16* Ql = sm + OFF_QL;
    __nv_bfloat16* Kh = sm + OFF_KH;
    __nv_bfloat16* Kl = sm + OFF_KL;
    __nv_bfloat16* Vh = sm + OFF_VH;
    __nv_bfloat16* Vl = sm + OFF_VL;
    __nv_bfloat16* Ph = sm + OFF_PH;
    __nv_bfloat16* Pl = sm + OFF_PL;

    const int tid  = threadIdx.x;
    const int lane = tid & 31;
    const int wid  = tid >> 5;
    const int wm   = (wid >> 2) * 64;   // warp q-row offset (0,64)
    const int wn   = (wid & 3);         // warp col group
    const int bh   = blockIdx.y;        // b*H + h
    const int q0   = blockIdx.x * 128;

    const float* Qp = Qg + (size_t)bh * S_ * DH_;
    const float* Kp = Kg + (size_t)bh * S_ * DH_;
    const float* Vp = Vg + (size_t)bh * S_ * DH_;

    // staging map for 128x64 fp32 tiles: 8 float4 per thread
    int srow[8], sc4[8];
#pragma unroll
    for (int i = 0; i < 8; i++) {
        const int idx = tid + i * 256;
        srow[i] = idx >> 4;
        sc4[i]  = (idx & 15) * 4;
    }

    // load + split Q tile
#pragma unroll
    for (int i = 0; i < 8; i++) {
        const float4 qv = *(const float4*)(Qp + (size_t)(q0 + srow[i]) * DH_ + sc4[i]);
        const int off = srow[i] * QST + sc4[i];
        uint32_t h, l;
        split2(qv.x, qv.y, h, l);
        *(uint32_t*)&Qh[off] = h; *(uint32_t*)&Ql[off] = l;
        split2(qv.z, qv.w, h, l);
        *(uint32_t*)&Qh[off + 2] = h; *(uint32_t*)&Ql[off + 2] = l;
    }

    // ldmatrix lane offsets
    const int a_r = lane & 15;
    const int a_k = (lane >> 4) * 8;
    const int b_r = (lane & 7) + ((lane >> 4) & 1) * 8;
    const int b_k = ((lane >> 3) & 1) * 8;
    // V trans lane offsets: kv row, dh col
    const int v_kv = (lane & 7) + ((lane & 8) ? 8 : 0);
    const int v_dh = ((lane >> 4) & 1) * 8;

    float oacc[4][2][4];
#pragma unroll
    for (int mt = 0; mt < 4; mt++)
#pragma unroll
        for (int nt = 0; nt < 2; nt++)
#pragma unroll
            for (int r = 0; r < 4; r++) oacc[mt][nt][r] = 0.0f;

    for (int j0 = 0; j0 < S_; j0 += 128) {
        __syncthreads();  // prior reads of K/V/P complete

        // load + split K,V tiles
#pragma unroll
        for (int i = 0; i < 8; i++) {
            const float4 kv4 = *(const float4*)(Kp + (size_t)(j0 + srow[i]) * DH_ + sc4[i]);
            const float4 vv4 = *(const float4*)(Vp + (size_t)(j0 + srow[i]) * DH_ + sc4[i]);
            const int off = srow[i] * QST + sc4[i];
            uint32_t h, l;
            split2(kv4.x, kv4.y, h, l);
            *(uint32_t*)&Kh[off] = h; *(uint32_t*)&Kl[off] = l;
            split2(kv4.z, kv4.w, h, l);
            *(uint32_t*)&Kh[off + 2] = h; *(uint32_t*)&Kl[off + 2] = l;
            split2(vv4.x, vv4.y, h, l);
            *(uint32_t*)&Vh[off] = h; *(uint32_t*)&Vl[off] = l;
            split2(vv4.z, vv4.w, h, l);
            *(uint32_t*)&Vh[off + 2] = h; *(uint32_t*)&Vl[off + 2] = l;
        }
        __syncthreads();

        // ---- Stage 1: S = Q K^T (warp tile 64x32) ----
        float sacc[4][4][4];
#pragma unroll
        for (int mt = 0; mt < 4; mt++)
#pragma unroll
            for (int nt = 0; nt < 4; nt++)
#pragma unroll
                for (int r = 0; r < 4; r++) sacc[mt][nt][r] = 0.0f;

#pragma unroll
        for (int ks = 0; ks < 4; ks++) {
            uint32_t Ahf[4][4], Alf[4][4], Bhf[4][2], Blf[4][2];
#pragma unroll
            for (int mt = 0; mt < 4; mt++) {
                const int eo = (wm + mt * 16 + a_r) * QST + ks * 16 + a_k;
                ldsm_x4(Ahf[mt][0], Ahf[mt][1], Ahf[mt][2], Ahf[mt][3], smem_u32(&Qh[eo]));
                ldsm_x4(Alf[mt][0], Alf[mt][1], Alf[mt][2], Alf[mt][3], smem_u32(&Ql[eo]));
            }
#pragma unroll
            for (int p = 0; p < 2; p++) {
                const int eo = (wn * 32 + p * 16 + b_r) * QST + ks * 16 + b_k;
                ldsm_x4(Bhf[2 * p][0], Bhf[2 * p][1], Bhf[2 * p + 1][0], Bhf[2 * p + 1][1],
                        smem_u32(&Kh[eo]));
                ldsm_x4(Blf[2 * p][0], Blf[2 * p][1], Blf[2 * p + 1][0], Blf[2 * p + 1][1],
                        smem_u32(&Kl[eo]));
            }
#pragma unroll
            for (int mt = 0; mt < 4; mt++)
#pragma unroll
                for (int nt = 0; nt < 4; nt++) {
                    mma_bf16(sacc[mt][nt], Ahf[mt], Bhf[nt]);
                    mma_bf16(sacc[mt][nt], Ahf[mt], Blf[nt]);
                    mma_bf16(sacc[mt][nt], Alf[mt], Bhf[nt]);
                }
        }

        // sigmoid(s/8), split, store P
#pragma unroll
        for (int mt = 0; mt < 4; mt++) {
            const int r0 = wm + mt * 16 + (lane >> 2);
#pragma unroll
            for (int nt = 0; nt < 4; nt++) {
                const int c0 = wn * 32 + nt * 8 + (lane & 3) * 2;
#pragma unroll
                for (int half = 0; half < 2; half++) {
                    const float x0 = sacc[mt][nt][2 * half]     * 0.125f;
                    const float x1 = sacc[mt][nt][2 * half + 1] * 0.125f;
                    const float p0 = __fdividef(1.0f, 1.0f + __expf(-x0));
                    const float p1 = __fdividef(1.0f, 1.0f + __expf(-x1));
                    uint32_t h, l;
                    split2(p0, p1, h, l);
                    const int off = (r0 + half * 8) * PST + c0;
                    *(uint32_t*)&Ph[off] = h;
                    *(uint32_t*)&Pl[off] = l;
                }
            }
        }
        __syncthreads();

        // ---- Stage 2: O += P V (warp tile 64x16, k = 128) ----
#pragma unroll
        for (int ks = 0; ks < 8; ks++) {
            uint32_t Ahf[4][4], Alf[4][4], Bhf[2][2], Blf[2][2];
#pragma unroll
            for (int mt = 0; mt < 4; mt++) {
                const int eo = (wm + mt * 16 + a_r) * PST + ks * 16 + a_k;
                ldsm_x4(Ahf[mt][0], Ahf[mt][1], Ahf[mt][2], Ahf[mt][3], smem_u32(&Ph[eo]));
                ldsm_x4(Alf[mt][0], Alf[mt][1], Alf[mt][2], Alf[mt][3], smem_u32(&Pl[eo]));
            }
            {
                const int eo = (ks * 16 + v_kv) * QST + wn * 16 + v_dh;
                ldsm_x4t(Bhf[0][0], Bhf[0][1], Bhf[1][0], Bhf[1][1], smem_u32(&Vh[eo]));
                ldsm_x4t(Blf[0][0], Blf[0][1], Blf[1][0], Blf[1][1], smem_u32(&Vl[eo]));
            }
#pragma unroll
            for (int mt = 0; mt < 4; mt++)
#pragma unroll
                for (int nt = 0; nt < 2; nt++) {
                    mma_bf16(oacc[mt][nt], Ahf[mt], Bhf[nt]);
                    mma_bf16(oacc[mt][nt], Ahf[mt], Blf[nt]);
                    mma_bf16(oacc[mt][nt], Alf[mt], Bhf[nt]);
                }
        }
    }

    // epilogue: write O to concat layout [B,S,D]
    const int bb = bh >> 4;
    const int h  = bh & (H_ - 1);
#pragma unroll
    for (int mt = 0; mt < 4; mt++) {
        const int s0 = q0 + wm + mt * 16 + (lane >> 2);
#pragma unroll
        for (int nt = 0; nt < 2; nt++) {
            const int dh = wn * 16 + nt * 8 + (lane & 3) * 2;
#pragma unroll
            for (int half = 0; half < 2; half++) {
                const int srw = s0 + half * 8;
                float2 w2 = make_float2(oacc[mt][nt][2 * half], oacc[mt][nt][2 * half + 1]);
                *(float2*)&Og[((size_t)bb * S_ + srw) * D_ + h * DH_ + dh] = w2;
            }
        }
    }
}

// ---------------------------------------------------------------------------
// Launcher
// ---------------------------------------------------------------------------
extern "C" void kernel_launch(void* const* d_in, const int* in_sizes, int n_in,
                              void* d_out, int out_size)
{
    const float* q  = (const float*)d_in[0];
    const float* k  = (const float*)d_in[1];
    const float* v  = (const float*)d_in[2];
    const float* Wq = (const float*)d_in[3];
    const float* bq = (const float*)d_in[4];
    const float* Wk = (const float*)d_in[5];
    const float* bk = (const float*)d_in[6];
    const float* Wv = (const float*)d_in[7];
    const float* bv = (const float*)d_in[8];
    const float* Wo = (const float*)d_in[9];
    const float* bo = (const float*)d_in[10];
    float* out = (float*)d_out;

    float *gq, *gk, *gv, *go;
    cudaGetSymbolAddress((void**)&gq, g_q);
    cudaGetSymbolAddress((void**)&gk, g_k);
    cudaGetSymbolAddress((void**)&gv, g_v);
    cudaGetSymbolAddress((void**)&go, g_o);

    const dim3 gg(D_ / 128, M_ / 128);  // (8, 64)

    gemm_mma<1><<<gg, 256>>>(q, Wq, bq, gq, M_, D_, D_);
    gemm_mma<1><<<gg, 256>>>(k, Wk, bk, gk, M_, D_, D_);
    gemm_mma<1><<<gg, 256>>>(v, Wv, bv, gv, M_, D_, D_);

    cudaFuncSetAttribute(attn_mma, cudaFuncAttributeMaxDynamicSharedMemorySize, ATTN_SMEM);
    attn_mma<<<dim3(S_ / 128, B_ * H_), 256, ATTN_SMEM>>>(gq, gk, gv, go);

    gemm_mma<0><<<gg, 256>>>(go, Wo, bo, out, M_, D_, D_);
}

// round 11
// speedup vs baseline: 2.4045x; 1.0008x over previous
#include <cuda_runtime.h>
#include <cuda_bf16.h>
#include <cstdint>

// Problem constants (fixed-shape problem)
#define B_  4
#define S_  2048
#define D_  1024
#define H_  16
#define DH_ 64
#define M_  (B_ * S_)   // 8192 rows for all projections

// ---------------------------------------------------------------------------
// Scratch (device globals: allocation-free, graph-capturable)
// ---------------------------------------------------------------------------
__device__ float g_q[B_ * H_ * S_ * DH_];
__device__ float g_k[B_ * H_ * S_ * DH_];
__device__ float g_v[B_ * H_ * S_ * DH_];
__device__ float g_o[B_ * S_ * D_];

// ---------------------------------------------------------------------------
// MMA helpers (bf16 HMMA, m16n8k16, fp32 accumulate)
// ---------------------------------------------------------------------------
__device__ __forceinline__ uint32_t smem_u32(const void* p) {
    return (uint32_t)__cvta_generic_to_shared(p);
}

__device__ __forceinline__ void ldsm_x4(uint32_t& r0, uint32_t& r1,
                                        uint32_t& r2, uint32_t& r3, uint32_t a) {
    asm volatile("ldmatrix.sync.aligned.m8n8.x4.shared.b16 {%0,%1,%2,%3}, [%4];"
                 : "=r"(r0), "=r"(r1), "=r"(r2), "=r"(r3) : "r"(a));
}
__device__ __forceinline__ void ldsm_x4t(uint32_t& r0, uint32_t& r1,
                                         uint32_t& r2, uint32_t& r3, uint32_t a) {
    asm volatile("ldmatrix.sync.aligned.m8n8.x4.trans.shared.b16 {%0,%1,%2,%3}, [%4];"
                 : "=r"(r0), "=r"(r1), "=r"(r2), "=r"(r3) : "r"(a));
}
__device__ __forceinline__ void mma_bf16(float* d, const uint32_t* a, const uint32_t* b) {
    asm volatile(
        "mma.sync.aligned.m16n8k16.row.col.f32.bf16.bf16.f32 "
        "{%0,%1,%2,%3}, {%4,%5,%6,%7}, {%8,%9}, {%0,%1,%2,%3};"
        : "+f"(d[0]), "+f"(d[1]), "+f"(d[2]), "+f"(d[3])
        : "r"(a[0]), "r"(a[1]), "r"(a[2]), "r"(a[3]), "r"(b[0]), "r"(b[1]));
}

// Split two fp32 into packed bf16 hi-pair and lo-pair (x in low half).
__device__ __forceinline__ void split2(float x, float y, uint32_t& hi, uint32_t& lo) {
    __nv_bfloat16 xh = __float2bfloat16(x);
    __nv_bfloat16 yh = __float2bfloat16(y);
    __nv_bfloat16 xl = __float2bfloat16(x - __bfloat162float(xh));
    __nv_bfloat16 yl = __float2bfloat16(y - __bfloat162float(yh));
    __nv_bfloat162 h2 = __halves2bfloat162(xh, yh);
    __nv_bfloat162 l2 = __halves2bfloat162(xl, yl);
    hi = *(uint32_t*)&h2;
    lo = *(uint32_t*)&l2;
}

// ---------------------------------------------------------------------------
// GEMM (NT): C[M,N] = A[M,K] * W[N,K]^T + bias[N]   (bf16x3 tensor path)
// MODE 0: C row-major [M,N]; MODE 1: scatter to [B,H,S,Dh]
// CTA 128x128, BK=32, 256 threads (8 warps, 2x4). fp32 gmem -> hi/lo bf16 smem.
// ---------------------------------------------------------------------------
#define AST 40   // smem K-stride (32 + 8 pad) in bf16 elems

template <int MODE>
__global__ __launch_bounds__(256) void gemm_mma(
    const float* __restrict__ A, const float* __restrict__ W,
    const float* __restrict__ bias, float* __restrict__ C,
    int M, int N, int K)
{
    __shared__ __align__(16) __nv_bfloat16 sAh[128 * AST];
    __shared__ __align__(16) __nv_bfloat16 sAl[128 * AST];
    __shared__ __align__(16) __nv_bfloat16 sWh[128 * AST];
    __shared__ __align__(16) __nv_bfloat16 sWl[128 * AST];

    const int tid  = threadIdx.x;
    const int lane = tid & 31;
    const int wid  = tid >> 5;
    const int wm   = (wid >> 2) * 64;   // warp M offset (0,64)
    const int wn   = (wid & 3) * 32;    // warp N offset (0..96)
    const int bm   = blockIdx.y * 128;
    const int bn   = blockIdx.x * 128;

    // gmem staging map: 4 float4 per thread per operand
    int srow[4], sc4[4];
#pragma unroll
    for (int i = 0; i < 4; i++) {
        const int idx = tid + i * 256;
        srow[i] = idx >> 3;
        sc4[i]  = (idx & 7) * 4;
    }

    float4 av[4], wv[4];
#pragma unroll
    for (int i = 0; i < 4; i++) {
        av[i] = *(const float4*)(A + (size_t)(bm + srow[i]) * K + sc4[i]);
        wv[i] = *(const float4*)(W + (size_t)(bn + srow[i]) * K + sc4[i]);
    }

    float acc[4][4][4];
#pragma unroll
    for (int mt = 0; mt < 4; mt++)
#pragma unroll
        for (int nt = 0; nt < 4; nt++)
#pragma unroll
            for (int r = 0; r < 4; r++) acc[mt][nt][r] = 0.0f;

    // ldmatrix source addresses (element offsets precomputed per lane)
    const int a_r = lane & 15;          // row within 16
    const int a_k = (lane >> 4) * 8;    // k offset 0/8
    const int b_r = (lane & 7) + ((lane >> 4) & 1) * 8;  // n within 16
    const int b_k = ((lane >> 3) & 1) * 8;               // k offset 0/8

    for (int k0 = 0; k0 < K; k0 += 32) {
        // stage current chunk into smem (split fp32 -> bf16 hi/lo)
#pragma unroll
        for (int i = 0; i < 4; i++) {
            const int off = srow[i] * AST + sc4[i];
            uint32_t h, l;
            split2(av[i].x, av[i].y, h, l);
            *(uint32_t*)&sAh[off] = h; *(uint32_t*)&sAl[off] = l;
            split2(av[i].z, av[i].w, h, l);
            *(uint32_t*)&sAh[off + 2] = h; *(uint32_t*)&sAl[off + 2] = l;
            split2(wv[i].x, wv[i].y, h, l);
            *(uint32_t*)&sWh[off] = h; *(uint32_t*)&sWl[off] = l;
            split2(wv[i].z, wv[i].w, h, l);
            *(uint32_t*)&sWh[off + 2] = h; *(uint32_t*)&sWl[off + 2] = l;
        }
        __syncthreads();

        if (k0 + 32 < K) {
#pragma unroll
            for (int i = 0; i < 4; i++) {
                av[i] = *(const float4*)(A + (size_t)(bm + srow[i]) * K + k0 + 32 + sc4[i]);
                wv[i] = *(const float4*)(W + (size_t)(bn + srow[i]) * K + k0 + 32 + sc4[i]);
            }
        }

#pragma unroll
        for (int ks = 0; ks < 2; ks++) {
            uint32_t Ah[4][4], Al[4][4], Bh[4][2], Bl[4][2];
#pragma unroll
            for (int mt = 0; mt < 4; mt++) {
                const int eo = (wm + mt * 16 + a_r) * AST + ks * 16 + a_k;
                ldsm_x4(Ah[mt][0], Ah[mt][1], Ah[mt][2], Ah[mt][3], smem_u32(&sAh[eo]));
                ldsm_x4(Al[mt][0], Al[mt][1], Al[mt][2], Al[mt][3], smem_u32(&sAl[eo]));
            }
#pragma unroll
            for (int p = 0; p < 2; p++) {
                const int eo = (wn + p * 16 + b_r) * AST + ks * 16 + b_k;
                ldsm_x4(Bh[2 * p][0], Bh[2 * p][1], Bh[2 * p + 1][0], Bh[2 * p + 1][1],
                        smem_u32(&sWh[eo]));
                ldsm_x4(Bl[2 * p][0], Bl[2 * p][1], Bl[2 * p + 1][0], Bl[2 * p + 1][1],
                        smem_u32(&sWl[eo]));
            }
#pragma unroll
            for (int mt = 0; mt < 4; mt++)
#pragma unroll
                for (int nt = 0; nt < 4; nt++) {
                    mma_bf16(acc[mt][nt], Ah[mt], Bh[nt]);
                    mma_bf16(acc[mt][nt], Ah[mt], Bl[nt]);
                    mma_bf16(acc[mt][nt], Al[mt], Bh[nt]);
                }
        }
        __syncthreads();
    }

    // epilogue from fragment layout
#pragma unroll
    for (int mt = 0; mt < 4; mt++) {
        const int r0 = bm + wm + mt * 16 + (lane >> 2);
#pragma unroll
        for (int nt = 0; nt < 4; nt++) {
            const int c0 = bn + wn + nt * 8 + (lane & 3) * 2;
            const float bz0 = bias[c0], bz1 = bias[c0 + 1];
#pragma unroll
            for (int half = 0; half < 2; half++) {
                const int row = r0 + half * 8;
                const float v0 = acc[mt][nt][2 * half]     + bz0;
                const float v1 = acc[mt][nt][2 * half + 1] + bz1;
                if (MODE == 0) {
                    C[(size_t)row * N + c0]     = v0;
                    C[(size_t)row * N + c0 + 1] = v1;
                } else {
                    const int bb = row >> 11;
                    const int ss = row & (S_ - 1);
                    const int h  = c0 >> 6;
                    const int dh = c0 & (DH_ - 1);
                    float* base = C + (((size_t)(bb * H_ + h)) * S_ + ss) * DH_ + dh;
                    base[0] = v0; base[1] = v1;
                }
            }
        }
    }
}

// ---------------------------------------------------------------------------
// Sigmoid attention (bf16x3 tensor path), per (b,h): O = sigmoid(QK^T/8) V
// Q tile 128, KV tile 128, Dh 64. 256 threads (8 warps, 2x4).
// smem: Q/K/V hi+lo [128][72] bf16, P hi+lo [128][136] bf16. 180224 B dynamic.
// ---------------------------------------------------------------------------
#define QST 72    // Q/K/V smem stride (64 + 8)
#define PST 136   // P smem stride (128 + 8)
#define OFF_QH 0
#define OFF_QL (128 * QST)
#define OFF_KH (2 * 128 * QST)
#define OFF_KL (3 * 128 * QST)
#define OFF_VH (4 * 128 * QST)
#define OFF_VL (5 * 128 * QST)
#define OFF_PH (6 * 128 * QST)
#define OFF_PL (6 * 128 * QST + 128 * PST)
#define ATTN_SMEM ((6 * 128 * QST + 2 * 128 * PST) * 2)

__global__ __launch_bounds__(256) void attn_mma(
    const float* __restrict__ Qg, const float* __restrict__ Kg,
    const float* __restrict__ Vg, float* __restrict__ Og)
{
    extern __shared__ __nv_bfloat16 sm[];
    __nv_bfloat16* Qh = sm + OFF_QH;
    __nv_bfloat16* Ql = sm + OFF_QL;
    __nv_bfloat16* Kh = sm + OFF_KH;
    __nv_bfloat16* Kl = sm + OFF_KL;
    __nv_bfloat16* Vh = sm + OFF_VH;
    __nv_bfloat16* Vl = sm + OFF_VL;
    __nv_bfloat16* Ph = sm + OFF_PH;
    __nv_bfloat16* Pl = sm + OFF_PL;

    const int tid  = threadIdx.x;
    const int lane = tid & 31;
    const int wid  = tid >> 5;
    const int wm   = (wid >> 2) * 64;   // warp q-row offset (0,64)
    const int wn   = (wid & 3);         // warp col group
    const int bh   = blockIdx.y;        // b*H + h
    const int q0   = blockIdx.x * 128;

    const float* Qp = Qg + (size_t)bh * S_ * DH_;
    const float* Kp = Kg + (size_t)bh * S_ * DH_;
    const float* Vp = Vg + (size_t)bh * S_ * DH_;

    // staging map for 128x64 fp32 tiles: 8 float4 per thread
    int srow[8], sc4[8];
#pragma unroll
    for (int i = 0; i < 8; i++) {
        const int idx = tid + i * 256;
        srow[i] = idx >> 4;
        sc4[i]  = (idx & 15) * 4;
    }

    // load + split Q tile
#pragma unroll
    for (int i = 0; i < 8; i++) {
        const float4 qv = *(const float4*)(Qp + (size_t)(q0 + srow[i]) * DH_ + sc4[i]);
        const int off = srow[i] * QST + sc4[i];
        uint32_t h, l;
        split2(qv.x, qv.y, h, l);
        *(uint32_t*)&Qh[off] = h; *(uint32_t*)&Ql[off] = l;
        split2(qv.z, qv.w, h, l);
        *(uint32_t*)&Qh[off + 2] = h; *(uint32_t*)&Ql[off + 2] = l;
    }

    // ldmatrix lane offsets
    const int a_r = lane & 15;
    const int a_k = (lane >> 4) * 8;
    const int b_r = (lane & 7) + ((lane >> 4) & 1) * 8;
    const int b_k = ((lane >> 3) & 1) * 8;
    // V trans lane offsets: kv row, dh col
    const int v_kv = (lane & 7) + ((lane & 8) ? 8 : 0);
    const int v_dh = ((lane >> 4) & 1) * 8;

    float oacc[4][2][4];
#pragma unroll
    for (int mt = 0; mt < 4; mt++)
#pragma unroll
        for (int nt = 0; nt < 2; nt++)
#pragma unroll
            for (int r = 0; r < 4; r++) oacc[mt][nt][r] = 0.0f;

    for (int j0 = 0; j0 < S_; j0 += 128) {
        __syncthreads();  // prior reads of K/V/P complete

        // load + split K,V tiles
#pragma unroll
        for (int i = 0; i < 8; i++) {
            const float4 kv4 = *(const float4*)(Kp + (size_t)(j0 + srow[i]) * DH_ + sc4[i]);
            const float4 vv4 = *(const float4*)(Vp + (size_t)(j0 + srow[i]) * DH_ + sc4[i]);
            const int off = srow[i] * QST + sc4[i];
            uint32_t h, l;
            split2(kv4.x, kv4.y, h, l);
            *(uint32_t*)&Kh[off] = h; *(uint32_t*)&Kl[off] = l;
            split2(kv4.z, kv4.w, h, l);
            *(uint32_t*)&Kh[off + 2] = h; *(uint32_t*)&Kl[off + 2] = l;
            split2(vv4.x, vv4.y, h, l);
            *(uint32_t*)&Vh[off] = h; *(uint32_t*)&Vl[off] = l;
            split2(vv4.z, vv4.w, h, l);
            *(uint32_t*)&Vh[off + 2] = h; *(uint32_t*)&Vl[off + 2] = l;
        }
        __syncthreads();

        // ---- Stage 1: S = Q K^T (warp tile 64x32) ----
        float sacc[4][4][4];
#pragma unroll
        for (int mt = 0; mt < 4; mt++)
#pragma unroll
            for (int nt = 0; nt < 4; nt++)
#pragma unroll
                for (int r = 0; r < 4; r++) sacc[mt][nt][r] = 0.0f;

#pragma unroll
        for (int ks = 0; ks < 4; ks++) {
            uint32_t Ahf[4][4], Alf[4][4], Bhf[4][2], Blf[4][2];
#pragma unroll
            for (int mt = 0; mt < 4; mt++) {
                const int eo = (wm + mt * 16 + a_r) * QST + ks * 16 + a_k;
                ldsm_x4(Ahf[mt][0], Ahf[mt][1], Ahf[mt][2], Ahf[mt][3], smem_u32(&Qh[eo]));
                ldsm_x4(Alf[mt][0], Alf[mt][1], Alf[mt][2], Alf[mt][3], smem_u32(&Ql[eo]));
            }
#pragma unroll
            for (int p = 0; p < 2; p++) {
                const int eo = (wn * 32 + p * 16 + b_r) * QST + ks * 16 + b_k;
                ldsm_x4(Bhf[2 * p][0], Bhf[2 * p][1], Bhf[2 * p + 1][0], Bhf[2 * p + 1][1],
                        smem_u32(&Kh[eo]));
                ldsm_x4(Blf[2 * p][0], Blf[2 * p][1], Blf[2 * p + 1][0], Blf[2 * p + 1][1],
                        smem_u32(&Kl[eo]));
            }
#pragma unroll
            for (int mt = 0; mt < 4; mt++)
#pragma unroll
                for (int nt = 0; nt < 4; nt++) {
                    mma_bf16(sacc[mt][nt], Ahf[mt], Bhf[nt]);
                    mma_bf16(sacc[mt][nt], Ahf[mt], Blf[nt]);
                    mma_bf16(sacc[mt][nt], Alf[mt], Bhf[nt]);
                }
        }

        // sigmoid(s/8), split, store P
#pragma unroll
        for (int mt = 0; mt < 4; mt++) {
            const int r0 = wm + mt * 16 + (lane >> 2);
#pragma unroll
            for (int nt = 0; nt < 4; nt++) {
                const int c0 = wn * 32 + nt * 8 + (lane & 3) * 2;
#pragma unroll
                for (int half = 0; half < 2; half++) {
                    const float x0 = sacc[mt][nt][2 * half]     * 0.125f;
                    const float x1 = sacc[mt][nt][2 * half + 1] * 0.125f;
                    const float p0 = __fdividef(1.0f, 1.0f + __expf(-x0));
                    const float p1 = __fdividef(1.0f, 1.0f + __expf(-x1));
                    uint32_t h, l;
                    split2(p0, p1, h, l);
                    const int off = (r0 + half * 8) * PST + c0;
                    *(uint32_t*)&Ph[off] = h;
                    *(uint32_t*)&Pl[off] = l;
                }
            }
        }
        __syncthreads();

        // ---- Stage 2: O += P V (warp tile 64x16, k = 128) ----
#pragma unroll
        for (int ks = 0; ks < 8; ks++) {
            uint32_t Ahf[4][4], Alf[4][4], Bhf[2][2], Blf[2][2];
#pragma unroll
            for (int mt = 0; mt < 4; mt++) {
                const int eo = (wm + mt * 16 + a_r) * PST + ks * 16 + a_k;
                ldsm_x4(Ahf[mt][0], Ahf[mt][1], Ahf[mt][2], Ahf[mt][3], smem_u32(&Ph[eo]));
                ldsm_x4(Alf[mt][0], Alf[mt][1], Alf[mt][2], Alf[mt][3], smem_u32(&Pl[eo]));
            }
            {
                const int eo = (ks * 16 + v_kv) * QST + wn * 16 + v_dh;
                ldsm_x4t(Bhf[0][0], Bhf[0][1], Bhf[1][0], Bhf[1][1], smem_u32(&Vh[eo]));
                ldsm_x4t(Blf[0][0], Blf[0][1], Blf[1][0], Blf[1][1], smem_u32(&Vl[eo]));
            }
#pragma unroll
            for (int mt = 0; mt < 4; mt++)
#pragma unroll
                for (int nt = 0; nt < 2; nt++) {
                    mma_bf16(oacc[mt][nt], Ahf[mt], Bhf[nt]);
                    mma_bf16(oacc[mt][nt], Ahf[mt], Blf[nt]);
                    mma_bf16(oacc[mt][nt], Alf[mt], Bhf[nt]);
                }
        }
    }

    // epilogue: write O to concat layout [B,S,D]
    const int bb = bh >> 4;
    const int h  = bh & (H_ - 1);
#pragma unroll
    for (int mt = 0; mt < 4; mt++) {
        const int s0 = q0 + wm + mt * 16 + (lane >> 2);
#pragma unroll
        for (int nt = 0; nt < 2; nt++) {
            const int dh = wn * 16 + nt * 8 + (lane & 3) * 2;
#pragma unroll
            for (int half = 0; half < 2; half++) {
                const int srw = s0 + half * 8;
                float2 w2 = make_float2(oacc[mt][nt][2 * half], oacc[mt][nt][2 * half + 1]);
                *(float2*)&Og[((size_t)bb * S_ + srw) * D_ + h * DH_ + dh] = w2;
            }
        }
    }
}

// ---------------------------------------------------------------------------
// Launcher
// ---------------------------------------------------------------------------
extern "C" void kernel_launch(void* const* d_in, const int* in_sizes, int n_in,
                              void* d_out, int out_size)
{
    const float* q  = (const float*)d_in[0];
    const float* k  = (const float*)d_in[1];
    const float* v  = (const float*)d_in[2];
    const float* Wq = (const float*)d_in[3];
    const float* bq = (const float*)d_in[4];
    const float* Wk = (const float*)d_in[5];
    const float* bk = (const float*)d_in[6];
    const float* Wv = (const float*)d_in[7];
    const float* bv = (const float*)d_in[8];
    const float* Wo = (const float*)d_in[9];
    const float* bo = (const float*)d_in[10];
    float* out = (float*)d_out;

    float *gq, *gk, *gv, *go;
    cudaGetSymbolAddress((void**)&gq, g_q);
    cudaGetSymbolAddress((void**)&gk, g_k);
    cudaGetSymbolAddress((void**)&gv, g_v);
    cudaGetSymbolAddress((void**)&go, g_o);

    const dim3 gg(D_ / 128, M_ / 128);  // (8, 64)

    gemm_mma<1><<<gg, 256>>>(q, Wq, bq, gq, M_, D_, D_);
    gemm_mma<1><<<gg, 256>>>(k, Wk, bk, gk, M_, D_, D_);
    gemm_mma<1><<<gg, 256>>>(v, Wv, bv, gv, M_, D_, D_);

    cudaFuncSetAttribute(attn_mma, cudaFuncAttributeMaxDynamicSharedMemorySize, ATTN_SMEM);
    attn_mma<<<dim3(S_ / 128, B_ * H_), 256, ATTN_SMEM>>>(gq, gk, gv, go);

    gemm_mma<0><<<gg, 256>>>(go, Wo, bo, out, M_, D_, D_);
}

// round 12
// speedup vs baseline: 2.6205x; 1.0899x over previous
#include <cuda_runtime.h>
#include <cuda_bf16.h>
#include <cstdint>

// Problem constants (fixed-shape problem)
#define B_  4
#define S_  2048
#define D_  1024
#define H_  16
#define DH_ 64
#define M_  (B_ * S_)   // 8192
#define MD_ (M_ * D_)   // 8388608
#define DD_ (D_ * D_)   // 1048576

// ---------------------------------------------------------------------------
// Scratch (device globals: allocation-free, graph-capturable)
// ---------------------------------------------------------------------------
__device__ __nv_bfloat16 g_inh[3 * MD_];  // split inputs (q,k,v) hi
__device__ __nv_bfloat16 g_inl[3 * MD_];  // lo
__device__ __nv_bfloat16 g_wh [4 * DD_];  // split weights (Wq,Wk,Wv,Wo) hi
__device__ __nv_bfloat16 g_wl [4 * DD_];
__device__ __nv_bfloat16 g_ph [3 * MD_];  // projected Q,K,V hi, [B,H,S,Dh]
__device__ __nv_bfloat16 g_pl [3 * MD_];
__device__ __nv_bfloat16 g_oh [MD_];      // attention output hi, [B,S,D]
__device__ __nv_bfloat16 g_ol [MD_];

// ---------------------------------------------------------------------------
// Helpers
// ---------------------------------------------------------------------------
__device__ __forceinline__ uint32_t smem_u32(const void* p) {
    return (uint32_t)__cvta_generic_to_shared(p);
}
__device__ __forceinline__ void ldsm_x4(uint32_t& r0, uint32_t& r1,
                                        uint32_t& r2, uint32_t& r3, uint32_t a) {
    asm volatile("ldmatrix.sync.aligned.m8n8.x4.shared.b16 {%0,%1,%2,%3}, [%4];"
                 : "=r"(r0), "=r"(r1), "=r"(r2), "=r"(r3) : "r"(a));
}
__device__ __forceinline__ void ldsm_x4t(uint32_t& r0, uint32_t& r1,
                                         uint32_t& r2, uint32_t& r3, uint32_t a) {
    asm volatile("ldmatrix.sync.aligned.m8n8.x4.trans.shared.b16 {%0,%1,%2,%3}, [%4];"
                 : "=r"(r0), "=r"(r1), "=r"(r2), "=r"(r3) : "r"(a));
}
__device__ __forceinline__ void mma_bf16(float* d, const uint32_t* a, const uint32_t* b) {
    asm volatile(
        "mma.sync.aligned.m16n8k16.row.col.f32.bf16.bf16.f32 "
        "{%0,%1,%2,%3}, {%4,%5,%6,%7}, {%8,%9}, {%0,%1,%2,%3};"
        : "+f"(d[0]), "+f"(d[1]), "+f"(d[2]), "+f"(d[3])
        : "r"(a[0]), "r"(a[1]), "r"(a[2]), "r"(a[3]), "r"(b[0]), "r"(b[1]));
}
// Split two fp32 into packed bf16 hi-pair and lo-pair (x in low half).
__device__ __forceinline__ void split2(float x, float y, uint32_t& hi, uint32_t& lo) {
    __nv_bfloat16 xh = __float2bfloat16(x);
    __nv_bfloat16 yh = __float2bfloat16(y);
    __nv_bfloat16 xl = __float2bfloat16(x - __bfloat162float(xh));
    __nv_bfloat16 yl = __float2bfloat16(y - __bfloat162float(yh));
    __nv_bfloat162 h2 = __halves2bfloat162(xh, yh);
    __nv_bfloat162 l2 = __halves2bfloat162(xl, yl);
    hi = *(uint32_t*)&h2;
    lo = *(uint32_t*)&l2;
}
__device__ __forceinline__ float sigm(float x) {
    return __fdividef(1.0f, 1.0f + __expf(-x * 0.125f));
}

// ---------------------------------------------------------------------------
// One-time fp32 -> bf16 hi/lo split (grid-stride, float4 granularity)
// ---------------------------------------------------------------------------
__global__ void split_kernel(const float* __restrict__ src,
                             __nv_bfloat16* __restrict__ hi,
                             __nv_bfloat16* __restrict__ lo, int n)
{
    for (int i = (blockIdx.x * blockDim.x + threadIdx.x) * 4; i < n;
         i += gridDim.x * blockDim.x * 4) {
        const float4 v = *(const float4*)(src + i);
        uint32_t h0, l0, h1, l1;
        split2(v.x, v.y, h0, l0);
        split2(v.z, v.w, h1, l1);
        *(uint2*)(hi + i) = make_uint2(h0, h1);
        *(uint2*)(lo + i) = make_uint2(l0, l1);
    }
}

// ---------------------------------------------------------------------------
// GEMM core (NT): C[M,N] = A[M,K] * W[N,K]^T + bias[N], bf16x3, pre-split in.
// M=8192, N=K=1024. CTA 128x128, BK=32, 256 threads (8 warps 2x4).
// MODE 0: C fp32 row-major. MODE 1: C split bf16 hi/lo, scatter [B,H,S,Dh].
// ---------------------------------------------------------------------------
#define AST 40   // smem K-stride (32 + 8 pad) bf16

template <int MODE>
__device__ __forceinline__ void gemm_core(
    const __nv_bfloat16* __restrict__ Ahg, const __nv_bfloat16* __restrict__ Alg,
    const __nv_bfloat16* __restrict__ Whg, const __nv_bfloat16* __restrict__ Wlg,
    const float* __restrict__ bias,
    float* __restrict__ Cf,
    __nv_bfloat16* __restrict__ Ch, __nv_bfloat16* __restrict__ Cl)
{
    __shared__ __align__(16) __nv_bfloat16 sAh[128 * AST];
    __shared__ __align__(16) __nv_bfloat16 sAl[128 * AST];
    __shared__ __align__(16) __nv_bfloat16 sWh[128 * AST];
    __shared__ __align__(16) __nv_bfloat16 sWl[128 * AST];

    const int tid  = threadIdx.x;
    const int lane = tid & 31;
    const int wid  = tid >> 5;
    const int wm   = (wid >> 2) * 64;
    const int wn   = (wid & 3) * 32;
    const int bm   = blockIdx.y * 128;
    const int bn   = blockIdx.x * 128;

    // staging map: per array, 2 uint4 (16B = 8 bf16) per thread per chunk
    int rrow[2], rq[2];
#pragma unroll
    for (int i = 0; i < 2; i++) {
        const int idx = tid + i * 256;
        rrow[i] = idx >> 2;
        rq[i]   = (idx & 3) * 8;
    }

    uint4 pah[2], pal[2], pwh[2], pwl[2];
#pragma unroll
    for (int i = 0; i < 2; i++) {
        pah[i] = *(const uint4*)(Ahg + (size_t)(bm + rrow[i]) * D_ + rq[i]);
        pal[i] = *(const uint4*)(Alg + (size_t)(bm + rrow[i]) * D_ + rq[i]);
        pwh[i] = *(const uint4*)(Whg + (size_t)(bn + rrow[i]) * D_ + rq[i]);
        pwl[i] = *(const uint4*)(Wlg + (size_t)(bn + rrow[i]) * D_ + rq[i]);
    }

    float acc[4][4][4];
#pragma unroll
    for (int mt = 0; mt < 4; mt++)
#pragma unroll
        for (int nt = 0; nt < 4; nt++)
#pragma unroll
            for (int r = 0; r < 4; r++) acc[mt][nt][r] = 0.0f;

    const int a_r = lane & 15;
    const int a_k = (lane >> 4) * 8;
    const int b_r = (lane & 7) + ((lane >> 4) & 1) * 8;
    const int b_k = ((lane >> 3) & 1) * 8;

    for (int k0 = 0; k0 < D_; k0 += 32) {
#pragma unroll
        for (int i = 0; i < 2; i++) {
            const int off = rrow[i] * AST + rq[i];
            *(uint4*)&sAh[off] = pah[i];
            *(uint4*)&sAl[off] = pal[i];
            *(uint4*)&sWh[off] = pwh[i];
            *(uint4*)&sWl[off] = pwl[i];
        }
        __syncthreads();

        if (k0 + 32 < D_) {
#pragma unroll
            for (int i = 0; i < 2; i++) {
                pah[i] = *(const uint4*)(Ahg + (size_t)(bm + rrow[i]) * D_ + k0 + 32 + rq[i]);
                pal[i] = *(const uint4*)(Alg + (size_t)(bm + rrow[i]) * D_ + k0 + 32 + rq[i]);
                pwh[i] = *(const uint4*)(Whg + (size_t)(bn + rrow[i]) * D_ + k0 + 32 + rq[i]);
                pwl[i] = *(const uint4*)(Wlg + (size_t)(bn + rrow[i]) * D_ + k0 + 32 + rq[i]);
            }
        }

#pragma unroll
        for (int ks = 0; ks < 2; ks++) {
            uint32_t Ah[4][4], Al[4][4], Bh[4][2], Bl[4][2];
#pragma unroll
            for (int mt = 0; mt < 4; mt++) {
                const int eo = (wm + mt * 16 + a_r) * AST + ks * 16 + a_k;
                ldsm_x4(Ah[mt][0], Ah[mt][1], Ah[mt][2], Ah[mt][3], smem_u32(&sAh[eo]));
                ldsm_x4(Al[mt][0], Al[mt][1], Al[mt][2], Al[mt][3], smem_u32(&sAl[eo]));
            }
#pragma unroll
            for (int p = 0; p < 2; p++) {
                const int eo = (wn + p * 16 + b_r) * AST + ks * 16 + b_k;
                ldsm_x4(Bh[2 * p][0], Bh[2 * p][1], Bh[2 * p + 1][0], Bh[2 * p + 1][1],
                        smem_u32(&sWh[eo]));
                ldsm_x4(Bl[2 * p][0], Bl[2 * p][1], Bl[2 * p + 1][0], Bl[2 * p + 1][1],
                        smem_u32(&sWl[eo]));
            }
#pragma unroll
            for (int mt = 0; mt < 4; mt++)
#pragma unroll
                for (int nt = 0; nt < 4; nt++) {
                    mma_bf16(acc[mt][nt], Ah[mt], Bh[nt]);
                    mma_bf16(acc[mt][nt], Ah[mt], Bl[nt]);
                    mma_bf16(acc[mt][nt], Al[mt], Bh[nt]);
                }
        }
        __syncthreads();
    }

    // epilogue
#pragma unroll
    for (int mt = 0; mt < 4; mt++) {
        const int r0 = bm + wm + mt * 16 + (lane >> 2);
#pragma unroll
        for (int nt = 0; nt < 4; nt++) {
            const int c0 = bn + wn + nt * 8 + (lane & 3) * 2;
            const float bz0 = bias[c0], bz1 = bias[c0 + 1];
#pragma unroll
            for (int half = 0; half < 2; half++) {
                const int row = r0 + half * 8;
                const float v0 = acc[mt][nt][2 * half]     + bz0;
                const float v1 = acc[mt][nt][2 * half + 1] + bz1;
                if (MODE == 0) {
                    *(float2*)&Cf[(size_t)row * D_ + c0] = make_float2(v0, v1);
                } else {
                    const int bb = row >> 11;
                    const int ss = row & (S_ - 1);
                    const int h  = c0 >> 6;
                    const int dh = c0 & (DH_ - 1);
                    const size_t o = (((size_t)(bb * H_ + h)) * S_ + ss) * DH_ + dh;
                    uint32_t hi, lo;
                    split2(v0, v1, hi, lo);
                    *(uint32_t*)&Ch[o] = hi;
                    *(uint32_t*)&Cl[o] = lo;
                }
            }
        }
    }
}

struct ProjArgs {
    const __nv_bfloat16 *Ah[3], *Al[3], *Wh[3], *Wl[3];
    const float* bias[3];
    __nv_bfloat16 *Ch[3], *Cl[3];
};

__global__ __launch_bounds__(256) void gemm_proj(ProjArgs pa)
{
    const int z = blockIdx.z;
    gemm_core<1>(pa.Ah[z], pa.Al[z], pa.Wh[z], pa.Wl[z], pa.bias[z],
                 nullptr, pa.Ch[z], pa.Cl[z]);
}

__global__ __launch_bounds__(256) void gemm_out(
    const __nv_bfloat16* __restrict__ Ah, const __nv_bfloat16* __restrict__ Al,
    const __nv_bfloat16* __restrict__ Wh, const __nv_bfloat16* __restrict__ Wl,
    const float* __restrict__ bias, float* __restrict__ C)
{
    gemm_core<0>(Ah, Al, Wh, Wl, bias, C, nullptr, nullptr);
}

// ---------------------------------------------------------------------------
// Sigmoid attention, FA2-style: per (b,h): O = sigmoid(QK^T/8) V
// Each warp owns 16 q-rows x full 128-kv tile; P (= sigmoid(S)) stays in
// registers: the m16n8 accumulator fragment pair re-packs directly into the
// m16k16 A-operand fragment (hi/lo bf16 split in regs). No P smem, 2 barriers
// per kv tile. smem = 6 x [128][72] bf16 = 110,592 B dynamic.
// ---------------------------------------------------------------------------
#define QST 72
#define ATT_SMEM (6 * 128 * QST * 2)

__global__ __launch_bounds__(256) void attn_fa(
    const __nv_bfloat16* __restrict__ Qh_g, const __nv_bfloat16* __restrict__ Ql_g,
    const __nv_bfloat16* __restrict__ Kh_g, const __nv_bfloat16* __restrict__ Kl_g,
    const __nv_bfloat16* __restrict__ Vh_g, const __nv_bfloat16* __restrict__ Vl_g,
    __nv_bfloat16* __restrict__ Oh_g, __nv_bfloat16* __restrict__ Ol_g)
{
    extern __shared__ __nv_bfloat16 sm[];
    __nv_bfloat16* Qh = sm;
    __nv_bfloat16* Ql = Qh + 128 * QST;
    __nv_bfloat16* Kh = Ql + 128 * QST;
    __nv_bfloat16* Kl = Kh + 128 * QST;
    __nv_bfloat16* Vh = Kl + 128 * QST;
    __nv_bfloat16* Vl = Vh + 128 * QST;

    const int tid  = threadIdx.x;
    const int lane = tid & 31;
    const int wid  = tid >> 5;
    const int r0   = wid * 16;           // warp's q-row block
    const int bh   = blockIdx.y;
    const int q0   = blockIdx.x * 128;

    const size_t base = (size_t)bh * S_ * DH_;
    const __nv_bfloat16* Qph = Qh_g + base;
    const __nv_bfloat16* Qpl = Ql_g + base;
    const __nv_bfloat16* Kph = Kh_g + base;
    const __nv_bfloat16* Kpl = Kl_g + base;
    const __nv_bfloat16* Vph = Vh_g + base;
    const __nv_bfloat16* Vpl = Vl_g + base;

    // staging map: per array, 4 uint4 per thread (128x64 bf16 tile)
    int srow[4], sq[4];
#pragma unroll
    for (int i = 0; i < 4; i++) {
        const int idx = tid + i * 256;
        srow[i] = idx >> 3;
        sq[i]   = (idx & 7) * 8;
    }

    // load Q hi/lo once
#pragma unroll
    for (int i = 0; i < 4; i++) {
        const size_t go = (size_t)(q0 + srow[i]) * DH_ + sq[i];
        const int    so = srow[i] * QST + sq[i];
        *(uint4*)&Qh[so] = *(const uint4*)(Qph + go);
        *(uint4*)&Ql[so] = *(const uint4*)(Qpl + go);
    }

    // ldmatrix lane offsets
    const int a_r = lane & 15;
    const int a_k = (lane >> 4) * 8;
    const int b_r = (lane & 7) + ((lane >> 4) & 1) * 8;
    const int b_k = ((lane >> 3) & 1) * 8;
    const int v_kv = lane & 15;
    const int v_dh = ((lane >> 4) & 1) * 8;

    float oacc[8][4];
#pragma unroll
    for (int t = 0; t < 8; t++)
#pragma unroll
        for (int r = 0; r < 4; r++) oacc[t][r] = 0.0f;

    for (int j0 = 0; j0 < S_; j0 += 128) {
        __syncthreads();   // prior tile's K/V reads complete
#pragma unroll
        for (int i = 0; i < 4; i++) {
            const size_t go = (size_t)(j0 + srow[i]) * DH_ + sq[i];
            const int    so = srow[i] * QST + sq[i];
            *(uint4*)&Kh[so] = *(const uint4*)(Kph + go);
            *(uint4*)&Kl[so] = *(const uint4*)(Kpl + go);
            *(uint4*)&Vh[so] = *(const uint4*)(Vph + go);
            *(uint4*)&Vl[so] = *(const uint4*)(Vpl + go);
        }
        __syncthreads();

        // ---- Stage 1: S rows r0..r0+15 x 128 kv ----
        float sacc[16][4];
#pragma unroll
        for (int t = 0; t < 16; t++)
#pragma unroll
            for (int r = 0; r < 4; r++) sacc[t][r] = 0.0f;

#pragma unroll
        for (int ks = 0; ks < 4; ks++) {
            uint32_t Afh[4], Afl[4];
            {
                const int eo = (r0 + a_r) * QST + ks * 16 + a_k;
                ldsm_x4(Afh[0], Afh[1], Afh[2], Afh[3], smem_u32(&Qh[eo]));
                ldsm_x4(Afl[0], Afl[1], Afl[2], Afl[3], smem_u32(&Ql[eo]));
            }
#pragma unroll
            for (int p = 0; p < 8; p++) {
                uint32_t Bh0[2], Bh1[2], Bl0[2], Bl1[2];
                const int eo = (p * 16 + b_r) * QST + ks * 16 + b_k;
                ldsm_x4(Bh0[0], Bh0[1], Bh1[0], Bh1[1], smem_u32(&Kh[eo]));
                ldsm_x4(Bl0[0], Bl0[1], Bl1[0], Bl1[1], smem_u32(&Kl[eo]));
                mma_bf16(sacc[2 * p],     Afh, Bh0);
                mma_bf16(sacc[2 * p],     Afh, Bl0);
                mma_bf16(sacc[2 * p],     Afl, Bh0);
                mma_bf16(sacc[2 * p + 1], Afh, Bh1);
                mma_bf16(sacc[2 * p + 1], Afh, Bl1);
                mma_bf16(sacc[2 * p + 1], Afl, Bh1);
            }
        }

        // sigmoid + repack accumulator fragments as A-operand fragments (hi/lo)
        uint32_t Pfh[8][4], Pfl[8][4];
#pragma unroll
        for (int kt = 0; kt < 8; kt++) {
            const int t0 = 2 * kt, t1 = 2 * kt + 1;
            const float p00 = sigm(sacc[t0][0]), p01 = sigm(sacc[t0][1]);
            const float p02 = sigm(sacc[t0][2]), p03 = sigm(sacc[t0][3]);
            const float p10 = sigm(sacc[t1][0]), p11 = sigm(sacc[t1][1]);
            const float p12 = sigm(sacc[t1][2]), p13 = sigm(sacc[t1][3]);
            split2(p00, p01, Pfh[kt][0], Pfl[kt][0]);
            split2(p02, p03, Pfh[kt][1], Pfl[kt][1]);
            split2(p10, p11, Pfh[kt][2], Pfl[kt][2]);
            split2(p12, p13, Pfh[kt][3], Pfl[kt][3]);
        }

        // ---- Stage 2: O += P V ----
#pragma unroll
        for (int kt = 0; kt < 8; kt++) {
#pragma unroll
            for (int nn = 0; nn < 4; nn++) {
                uint32_t Bh0[2], Bh1[2], Bl0[2], Bl1[2];
                const int eo = (kt * 16 + v_kv) * QST + nn * 16 + v_dh;
                ldsm_x4t(Bh0[0], Bh0[1], Bh1[0], Bh1[1], smem_u32(&Vh[eo]));
                ldsm_x4t(Bl0[0], Bl0[1], Bl1[0], Bl1[1], smem_u32(&Vl[eo]));
                mma_bf16(oacc[2 * nn],     Pfh[kt], Bh0);
                mma_bf16(oacc[2 * nn],     Pfh[kt], Bl0);
                mma_bf16(oacc[2 * nn],     Pfl[kt], Bh0);
                mma_bf16(oacc[2 * nn + 1], Pfh[kt], Bh1);
                mma_bf16(oacc[2 * nn + 1], Pfh[kt], Bl1);
                mma_bf16(oacc[2 * nn + 1], Pfl[kt], Bh1);
            }
        }
    }

    // epilogue: split O -> hi/lo bf16, concat layout [B,S,D]
    const int bb = bh >> 4;
    const int h  = bh & (H_ - 1);
    const int g  = lane >> 2;
    const int c2 = (lane & 3) * 2;
#pragma unroll
    for (int t = 0; t < 8; t++) {
        const int dh = 8 * t + c2;
#pragma unroll
        for (int half = 0; half < 2; half++) {
            const int srw = q0 + r0 + g + half * 8;
            const size_t o = ((size_t)bb * S_ + srw) * D_ + h * DH_ + dh;
            uint32_t hi, lo;
            split2(oacc[t][2 * half], oacc[t][2 * half + 1], hi, lo);
            *(uint32_t*)&Oh_g[o] = hi;
            *(uint32_t*)&Ol_g[o] = lo;
        }
    }
}

// ---------------------------------------------------------------------------
// Launcher
// ---------------------------------------------------------------------------
extern "C" void kernel_launch(void* const* d_in, const int* in_sizes, int n_in,
                              void* d_out, int out_size)
{
    const float* q  = (const float*)d_in[0];
    const float* k  = (const float*)d_in[1];
    const float* v  = (const float*)d_in[2];
    const float* Wq = (const float*)d_in[3];
    const float* bq = (const float*)d_in[4];
    const float* Wk = (const float*)d_in[5];
    const float* bk = (const float*)d_in[6];
    const float* Wv = (const float*)d_in[7];
    const float* bv = (const float*)d_in[8];
    const float* Wo = (const float*)d_in[9];
    const float* bo = (const float*)d_in[10];
    float* out = (float*)d_out;

    __nv_bfloat16 *inh, *inl, *wh, *wl, *ph, *pl, *oh, *ol;
    cudaGetSymbolAddress((void**)&inh, g_inh);
    cudaGetSymbolAddress((void**)&inl, g_inl);
    cudaGetSymbolAddress((void**)&wh,  g_wh);
    cudaGetSymbolAddress((void**)&wl,  g_wl);
    cudaGetSymbolAddress((void**)&ph,  g_ph);
    cudaGetSymbolAddress((void**)&pl,  g_pl);
    cudaGetSymbolAddress((void**)&oh,  g_oh);
    cudaGetSymbolAddress((void**)&ol,  g_ol);

    // one-time splits
    split_kernel<<<2048, 256>>>(q,  inh + 0 * MD_, inl + 0 * MD_, MD_);
    split_kernel<<<2048, 256>>>(k,  inh + 1 * MD_, inl + 1 * MD_, MD_);
    split_kernel<<<2048, 256>>>(v,  inh + 2 * MD_, inl + 2 * MD_, MD_);
    split_kernel<<<512, 256>>>(Wq, wh + 0 * DD_, wl + 0 * DD_, DD_);
    split_kernel<<<512, 256>>>(Wk, wh + 1 * DD_, wl + 1 * DD_, DD_);
    split_kernel<<<512, 256>>>(Wv, wh + 2 * DD_, wl + 2 * DD_, DD_);
    split_kernel<<<512, 256>>>(Wo, wh + 3 * DD_, wl + 3 * DD_, DD_);

    // fused Q/K/V projections (grid.z = 3)
    ProjArgs pa;
    const float* biases[3] = {bq, bk, bv};
    for (int z = 0; z < 3; z++) {
        pa.Ah[z] = inh + (size_t)z * MD_;
        pa.Al[z] = inl + (size_t)z * MD_;
        pa.Wh[z] = wh + (size_t)z * DD_;
        pa.Wl[z] = wl + (size_t)z * DD_;
        pa.bias[z] = biases[z];
        pa.Ch[z] = ph + (size_t)z * MD_;
        pa.Cl[z] = pl + (size_t)z * MD_;
    }
    gemm_proj<<<dim3(D_ / 128, M_ / 128, 3), 256>>>(pa);

    // attention
    cudaFuncSetAttribute(attn_fa, cudaFuncAttributeMaxDynamicSharedMemorySize, ATT_SMEM);
    attn_fa<<<dim3(S_ / 128, B_ * H_), 256, ATT_SMEM>>>(
        ph + 0 * MD_, pl + 0 * MD_,
        ph + 1 * MD_, pl + 1 * MD_,
        ph + 2 * MD_, pl + 2 * MD_,
        oh, ol);

    // output projection
    gemm_out<<<dim3(D_ / 128, M_ / 128), 256>>>(oh, ol, wh + 3 * DD_, wl + 3 * DD_, bo, out);
}

// round 13
// speedup vs baseline: 2.6239x; 1.0013x over previous
#include <cuda_runtime.h>
#include <cuda_bf16.h>
#include <cstdint>

// Problem constants (fixed-shape problem)
#define B_  4
#define S_  2048
#define D_  1024
#define H_  16
#define DH_ 64
#define M_  (B_ * S_)   // 8192
#define MD_ (M_ * D_)   // 8388608
#define DD_ (D_ * D_)   // 1048576

// ---------------------------------------------------------------------------
// Scratch (device globals: allocation-free, graph-capturable)
// ---------------------------------------------------------------------------
__device__ __nv_bfloat16 g_inh[3 * MD_];  // split inputs (q,k,v) hi
__device__ __nv_bfloat16 g_inl[3 * MD_];  // lo
__device__ __nv_bfloat16 g_wh [4 * DD_];  // split weights (Wq,Wk,Wv,Wo) hi
__device__ __nv_bfloat16 g_wl [4 * DD_];
__device__ __nv_bfloat16 g_ph [3 * MD_];  // projected Q,K,V hi, [B,H,S,Dh]
__device__ __nv_bfloat16 g_pl [3 * MD_];
__device__ __nv_bfloat16 g_oh [MD_];      // attention output hi, [B,S,D]
__device__ __nv_bfloat16 g_ol [MD_];

// ---------------------------------------------------------------------------
// Helpers
// ---------------------------------------------------------------------------
__device__ __forceinline__ uint32_t smem_u32(const void* p) {
    return (uint32_t)__cvta_generic_to_shared(p);
}
__device__ __forceinline__ void ldsm_x4(uint32_t& r0, uint32_t& r1,
                                        uint32_t& r2, uint32_t& r3, uint32_t a) {
    asm volatile("ldmatrix.sync.aligned.m8n8.x4.shared.b16 {%0,%1,%2,%3}, [%4];"
                 : "=r"(r0), "=r"(r1), "=r"(r2), "=r"(r3) : "r"(a));
}
__device__ __forceinline__ void ldsm_x4t(uint32_t& r0, uint32_t& r1,
                                         uint32_t& r2, uint32_t& r3, uint32_t a) {
    asm volatile("ldmatrix.sync.aligned.m8n8.x4.trans.shared.b16 {%0,%1,%2,%3}, [%4];"
                 : "=r"(r0), "=r"(r1), "=r"(r2), "=r"(r3) : "r"(a));
}
__device__ __forceinline__ void mma_bf16(float* d, const uint32_t* a, const uint32_t* b) {
    asm volatile(
        "mma.sync.aligned.m16n8k16.row.col.f32.bf16.bf16.f32 "
        "{%0,%1,%2,%3}, {%4,%5,%6,%7}, {%8,%9}, {%0,%1,%2,%3};"
        : "+f"(d[0]), "+f"(d[1]), "+f"(d[2]), "+f"(d[3])
        : "r"(a[0]), "r"(a[1]), "r"(a[2]), "r"(a[3]), "r"(b[0]), "r"(b[1]));
}
// Split two fp32 into packed bf16 hi-pair and lo-pair (x in low half).
__device__ __forceinline__ void split2(float x, float y, uint32_t& hi, uint32_t& lo) {
    __nv_bfloat16 xh = __float2bfloat16(x);
    __nv_bfloat16 yh = __float2bfloat16(y);
    __nv_bfloat16 xl = __float2bfloat16(x - __bfloat162float(xh));
    __nv_bfloat16 yl = __float2bfloat16(y - __bfloat162float(yh));
    __nv_bfloat162 h2 = __halves2bfloat162(xh, yh);
    __nv_bfloat162 l2 = __halves2bfloat162(xl, yl);
    hi = *(uint32_t*)&h2;
    lo = *(uint32_t*)&l2;
}
__device__ __forceinline__ float sigm(float x) {
    return __fdividef(1.0f, 1.0f + __expf(-x * 0.125f));
}

// ---------------------------------------------------------------------------
// One-time fp32 -> bf16 hi/lo split (grid-stride, float4 granularity)
// ---------------------------------------------------------------------------
__global__ void split_kernel(const float* __restrict__ src,
                             __nv_bfloat16* __restrict__ hi,
                             __nv_bfloat16* __restrict__ lo, int n)
{
    for (int i = (blockIdx.x * blockDim.x + threadIdx.x) * 4; i < n;
         i += gridDim.x * blockDim.x * 4) {
        const float4 v = *(const float4*)(src + i);
        uint32_t h0, l0, h1, l1;
        split2(v.x, v.y, h0, l0);
        split2(v.z, v.w, h1, l1);
        *(uint2*)(hi + i) = make_uint2(h0, h1);
        *(uint2*)(lo + i) = make_uint2(l0, l1);
    }
}

// ---------------------------------------------------------------------------
// GEMM core (NT): C[M,N] = A[M,K] * W[N,K]^T + bias[N], bf16x3, pre-split in.
// M=8192, N=K=1024. CTA 128x128, BK=32, 256 threads (8 warps 2x4).
// MODE 0: C fp32 row-major. MODE 1: C split bf16 hi/lo, scatter [B,H,S,Dh].
// ---------------------------------------------------------------------------
#define AST 40   // smem K-stride (32 + 8 pad) bf16

template <int MODE>
__device__ __forceinline__ void gemm_core(
    const __nv_bfloat16* __restrict__ Ahg, const __nv_bfloat16* __restrict__ Alg,
    const __nv_bfloat16* __restrict__ Whg, const __nv_bfloat16* __restrict__ Wlg,
    const float* __restrict__ bias,
    float* __restrict__ Cf,
    __nv_bfloat16* __restrict__ Ch, __nv_bfloat16* __restrict__ Cl)
{
    __shared__ __align__(16) __nv_bfloat16 sAh[128 * AST];
    __shared__ __align__(16) __nv_bfloat16 sAl[128 * AST];
    __shared__ __align__(16) __nv_bfloat16 sWh[128 * AST];
    __shared__ __align__(16) __nv_bfloat16 sWl[128 * AST];

    const int tid  = threadIdx.x;
    const int lane = tid & 31;
    const int wid  = tid >> 5;
    const int wm   = (wid >> 2) * 64;
    const int wn   = (wid & 3) * 32;
    const int bm   = blockIdx.y * 128;
    const int bn   = blockIdx.x * 128;

    // staging map: per array, 2 uint4 (16B = 8 bf16) per thread per chunk
    int rrow[2], rq[2];
#pragma unroll
    for (int i = 0; i < 2; i++) {
        const int idx = tid + i * 256;
        rrow[i] = idx >> 2;
        rq[i]   = (idx & 3) * 8;
    }

    uint4 pah[2], pal[2], pwh[2], pwl[2];
#pragma unroll
    for (int i = 0; i < 2; i++) {
        pah[i] = *(const uint4*)(Ahg + (size_t)(bm + rrow[i]) * D_ + rq[i]);
        pal[i] = *(const uint4*)(Alg + (size_t)(bm + rrow[i]) * D_ + rq[i]);
        pwh[i] = *(const uint4*)(Whg + (size_t)(bn + rrow[i]) * D_ + rq[i]);
        pwl[i] = *(const uint4*)(Wlg + (size_t)(bn + rrow[i]) * D_ + rq[i]);
    }

    float acc[4][4][4];
#pragma unroll
    for (int mt = 0; mt < 4; mt++)
#pragma unroll
        for (int nt = 0; nt < 4; nt++)
#pragma unroll
            for (int r = 0; r < 4; r++) acc[mt][nt][r] = 0.0f;

    const int a_r = lane & 15;
    const int a_k = (lane >> 4) * 8;
    const int b_r = (lane & 7) + ((lane >> 4) & 1) * 8;
    const int b_k = ((lane >> 3) & 1) * 8;

    for (int k0 = 0; k0 < D_; k0 += 32) {
#pragma unroll
        for (int i = 0; i < 2; i++) {
            const int off = rrow[i] * AST + rq[i];
            *(uint4*)&sAh[off] = pah[i];
            *(uint4*)&sAl[off] = pal[i];
            *(uint4*)&sWh[off] = pwh[i];
            *(uint4*)&sWl[off] = pwl[i];
        }
        __syncthreads();

        if (k0 + 32 < D_) {
#pragma unroll
            for (int i = 0; i < 2; i++) {
                pah[i] = *(const uint4*)(Ahg + (size_t)(bm + rrow[i]) * D_ + k0 + 32 + rq[i]);
                pal[i] = *(const uint4*)(Alg + (size_t)(bm + rrow[i]) * D_ + k0 + 32 + rq[i]);
                pwh[i] = *(const uint4*)(Whg + (size_t)(bn + rrow[i]) * D_ + k0 + 32 + rq[i]);
                pwl[i] = *(const uint4*)(Wlg + (size_t)(bn + rrow[i]) * D_ + k0 + 32 + rq[i]);
            }
        }

#pragma unroll
        for (int ks = 0; ks < 2; ks++) {
            uint32_t Ah[4][4], Al[4][4], Bh[4][2], Bl[4][2];
#pragma unroll
            for (int mt = 0; mt < 4; mt++) {
                const int eo = (wm + mt * 16 + a_r) * AST + ks * 16 + a_k;
                ldsm_x4(Ah[mt][0], Ah[mt][1], Ah[mt][2], Ah[mt][3], smem_u32(&sAh[eo]));
                ldsm_x4(Al[mt][0], Al[mt][1], Al[mt][2], Al[mt][3], smem_u32(&sAl[eo]));
            }
#pragma unroll
            for (int p = 0; p < 2; p++) {
                const int eo = (wn + p * 16 + b_r) * AST + ks * 16 + b_k;
                ldsm_x4(Bh[2 * p][0], Bh[2 * p][1], Bh[2 * p + 1][0], Bh[2 * p + 1][1],
                        smem_u32(&sWh[eo]));
                ldsm_x4(Bl[2 * p][0], Bl[2 * p][1], Bl[2 * p + 1][0], Bl[2 * p + 1][1],
                        smem_u32(&sWl[eo]));
            }
#pragma unroll
            for (int mt = 0; mt < 4; mt++)
#pragma unroll
                for (int nt = 0; nt < 4; nt++) {
                    mma_bf16(acc[mt][nt], Ah[mt], Bh[nt]);
                    mma_bf16(acc[mt][nt], Ah[mt], Bl[nt]);
                    mma_bf16(acc[mt][nt], Al[mt], Bh[nt]);
                }
        }
        __syncthreads();
    }

    // epilogue
#pragma unroll
    for (int mt = 0; mt < 4; mt++) {
        const int r0 = bm + wm + mt * 16 + (lane >> 2);
#pragma unroll
        for (int nt = 0; nt < 4; nt++) {
            const int c0 = bn + wn + nt * 8 + (lane & 3) * 2;
            const float bz0 = bias[c0], bz1 = bias[c0 + 1];
#pragma unroll
            for (int half = 0; half < 2; half++) {
                const int row = r0 + half * 8;
                const float v0 = acc[mt][nt][2 * half]     + bz0;
                const float v1 = acc[mt][nt][2 * half + 1] + bz1;
                if (MODE == 0) {
                    *(float2*)&Cf[(size_t)row * D_ + c0] = make_float2(v0, v1);
                } else {
                    const int bb = row >> 11;
                    const int ss = row & (S_ - 1);
                    const int h  = c0 >> 6;
                    const int dh = c0 & (DH_ - 1);
                    const size_t o = (((size_t)(bb * H_ + h)) * S_ + ss) * DH_ + dh;
                    uint32_t hi, lo;
                    split2(v0, v1, hi, lo);
                    *(uint32_t*)&Ch[o] = hi;
                    *(uint32_t*)&Cl[o] = lo;
                }
            }
        }
    }
}

struct ProjArgs {
    const __nv_bfloat16 *Ah[3], *Al[3], *Wh[3], *Wl[3];
    const float* bias[3];
    __nv_bfloat16 *Ch[3], *Cl[3];
};

__global__ __launch_bounds__(256) void gemm_proj(ProjArgs pa)
{
    const int z = blockIdx.z;
    gemm_core<1>(pa.Ah[z], pa.Al[z], pa.Wh[z], pa.Wl[z], pa.bias[z],
                 nullptr, pa.Ch[z], pa.Cl[z]);
}

__global__ __launch_bounds__(256) void gemm_out(
    const __nv_bfloat16* __restrict__ Ah, const __nv_bfloat16* __restrict__ Al,
    const __nv_bfloat16* __restrict__ Wh, const __nv_bfloat16* __restrict__ Wl,
    const float* __restrict__ bias, float* __restrict__ C)
{
    gemm_core<0>(Ah, Al, Wh, Wl, bias, C, nullptr, nullptr);
}

// ---------------------------------------------------------------------------
// Sigmoid attention, FA2-style: per (b,h): O = sigmoid(QK^T/8) V
// Each warp owns 16 q-rows x full 128-kv tile; P (= sigmoid(S)) stays in
// registers: the m16n8 accumulator fragment pair re-packs directly into the
// m16k16 A-operand fragment (hi/lo bf16 split in regs). No P smem, 2 barriers
// per kv tile. smem = 6 x [128][72] bf16 = 110,592 B dynamic.
// ---------------------------------------------------------------------------
#define QST 72
#define ATT_SMEM (6 * 128 * QST * 2)

__global__ __launch_bounds__(256) void attn_fa(
    const __nv_bfloat16* __restrict__ Qh_g, const __nv_bfloat16* __restrict__ Ql_g,
    const __nv_bfloat16* __restrict__ Kh_g, const __nv_bfloat16* __restrict__ Kl_g,
    const __nv_bfloat16* __restrict__ Vh_g, const __nv_bfloat16* __restrict__ Vl_g,
    __nv_bfloat16* __restrict__ Oh_g, __nv_bfloat16* __restrict__ Ol_g)
{
    extern __shared__ __nv_bfloat16 sm[];
    __nv_bfloat16* Qh = sm;
    __nv_bfloat16* Ql = Qh + 128 * QST;
    __nv_bfloat16* Kh = Ql + 128 * QST;
    __nv_bfloat16* Kl = Kh + 128 * QST;
    __nv_bfloat16* Vh = Kl + 128 * QST;
    __nv_bfloat16* Vl = Vh + 128 * QST;

    const int tid  = threadIdx.x;
    const int lane = tid & 31;
    const int wid  = tid >> 5;
    const int r0   = wid * 16;           // warp's q-row block
    const int bh   = blockIdx.y;
    const int q0   = blockIdx.x * 128;

    const size_t base = (size_t)bh * S_ * DH_;
    const __nv_bfloat16* Qph = Qh_g + base;
    const __nv_bfloat16* Qpl = Ql_g + base;
    const __nv_bfloat16* Kph = Kh_g + base;
    const __nv_bfloat16* Kpl = Kl_g + base;
    const __nv_bfloat16* Vph = Vh_g + base;
    const __nv_bfloat16* Vpl = Vl_g + base;

    // staging map: per array, 4 uint4 per thread (128x64 bf16 tile)
    int srow[4], sq[4];
#pragma unroll
    for (int i = 0; i < 4; i++) {
        const int idx = tid + i * 256;
        srow[i] = idx >> 3;
        sq[i]   = (idx & 7) * 8;
    }

    // load Q hi/lo once
#pragma unroll
    for (int i = 0; i < 4; i++) {
        const size_t go = (size_t)(q0 + srow[i]) * DH_ + sq[i];
        const int    so = srow[i] * QST + sq[i];
        *(uint4*)&Qh[so] = *(const uint4*)(Qph + go);
        *(uint4*)&Ql[so] = *(const uint4*)(Qpl + go);
    }

    // ldmatrix lane offsets
    const int a_r = lane & 15;
    const int a_k = (lane >> 4) * 8;
    const int b_r = (lane & 7) + ((lane >> 4) & 1) * 8;
    const int b_k = ((lane >> 3) & 1) * 8;
    const int v_kv = lane & 15;
    const int v_dh = ((lane >> 4) & 1) * 8;

    float oacc[8][4];
#pragma unroll
    for (int t = 0; t < 8; t++)
#pragma unroll
        for (int r = 0; r < 4; r++) oacc[t][r] = 0.0f;

    for (int j0 = 0; j0 < S_; j0 += 128) {
        __syncthreads();   // prior tile's K/V reads complete
#pragma unroll
        for (int i = 0; i < 4; i++) {
            const size_t go = (size_t)(j0 + srow[i]) * DH_ + sq[i];
            const int    so = srow[i] * QST + sq[i];
            *(uint4*)&Kh[so] = *(const uint4*)(Kph + go);
            *(uint4*)&Kl[so] = *(const uint4*)(Kpl + go);
            *(uint4*)&Vh[so] = *(const uint4*)(Vph + go);
            *(uint4*)&Vl[so] = *(const uint4*)(Vpl + go);
        }
        __syncthreads();

        // ---- Stage 1: S rows r0..r0+15 x 128 kv ----
        float sacc[16][4];
#pragma unroll
        for (int t = 0; t < 16; t++)
#pragma unroll
            for (int r = 0; r < 4; r++) sacc[t][r] = 0.0f;

#pragma unroll
        for (int ks = 0; ks < 4; ks++) {
            uint32_t Afh[4], Afl[4];
            {
                const int eo = (r0 + a_r) * QST + ks * 16 + a_k;
                ldsm_x4(Afh[0], Afh[1], Afh[2], Afh[3], smem_u32(&Qh[eo]));
                ldsm_x4(Afl[0], Afl[1], Afl[2], Afl[3], smem_u32(&Ql[eo]));
            }
#pragma unroll
            for (int p = 0; p < 8; p++) {
                uint32_t Bh0[2], Bh1[2], Bl0[2], Bl1[2];
                const int eo = (p * 16 + b_r) * QST + ks * 16 + b_k;
                ldsm_x4(Bh0[0], Bh0[1], Bh1[0], Bh1[1], smem_u32(&Kh[eo]));
                ldsm_x4(Bl0[0], Bl0[1], Bl1[0], Bl1[1], smem_u32(&Kl[eo]));
                mma_bf16(sacc[2 * p],     Afh, Bh0);
                mma_bf16(sacc[2 * p],     Afh, Bl0);
                mma_bf16(sacc[2 * p],     Afl, Bh0);
                mma_bf16(sacc[2 * p + 1], Afh, Bh1);
                mma_bf16(sacc[2 * p + 1], Afh, Bl1);
                mma_bf16(sacc[2 * p + 1], Afl, Bh1);
            }
        }

        // sigmoid + repack accumulator fragments as A-operand fragments (hi/lo)
        uint32_t Pfh[8][4], Pfl[8][4];
#pragma unroll
        for (int kt = 0; kt < 8; kt++) {
            const int t0 = 2 * kt, t1 = 2 * kt + 1;
            const float p00 = sigm(sacc[t0][0]), p01 = sigm(sacc[t0][1]);
            const float p02 = sigm(sacc[t0][2]), p03 = sigm(sacc[t0][3]);
            const float p10 = sigm(sacc[t1][0]), p11 = sigm(sacc[t1][1]);
            const float p12 = sigm(sacc[t1][2]), p13 = sigm(sacc[t1][3]);
            split2(p00, p01, Pfh[kt][0], Pfl[kt][0]);
            split2(p02, p03, Pfh[kt][1], Pfl[kt][1]);
            split2(p10, p11, Pfh[kt][2], Pfl[kt][2]);
            split2(p12, p13, Pfh[kt][3], Pfl[kt][3]);
        }

        // ---- Stage 2: O += P V ----
#pragma unroll
        for (int kt = 0; kt < 8; kt++) {
#pragma unroll
            for (int nn = 0; nn < 4; nn++) {
                uint32_t Bh0[2], Bh1[2], Bl0[2], Bl1[2];
                const int eo = (kt * 16 + v_kv) * QST + nn * 16 + v_dh;
                ldsm_x4t(Bh0[0], Bh0[1], Bh1[0], Bh1[1], smem_u32(&Vh[eo]));
                ldsm_x4t(Bl0[0], Bl0[1], Bl1[0], Bl1[1], smem_u32(&Vl[eo]));
                mma_bf16(oacc[2 * nn],     Pfh[kt], Bh0);
                mma_bf16(oacc[2 * nn],     Pfh[kt], Bl0);
                mma_bf16(oacc[2 * nn],     Pfl[kt], Bh0);
                mma_bf16(oacc[2 * nn + 1], Pfh[kt], Bh1);
                mma_bf16(oacc[2 * nn + 1], Pfh[kt], Bl1);
                mma_bf16(oacc[2 * nn + 1], Pfl[kt], Bh1);
            }
        }
    }

    // epilogue: split O -> hi/lo bf16, concat layout [B,S,D]
    const int bb = bh >> 4;
    const int h  = bh & (H_ - 1);
    const int g  = lane >> 2;
    const int c2 = (lane & 3) * 2;
#pragma unroll
    for (int t = 0; t < 8; t++) {
        const int dh = 8 * t + c2;
#pragma unroll
        for (int half = 0; half < 2; half++) {
            const int srw = q0 + r0 + g + half * 8;
            const size_t o = ((size_t)bb * S_ + srw) * D_ + h * DH_ + dh;
            uint32_t hi, lo;
            split2(oacc[t][2 * half], oacc[t][2 * half + 1], hi, lo);
            *(uint32_t*)&Oh_g[o] = hi;
            *(uint32_t*)&Ol_g[o] = lo;
        }
    }
}

// ---------------------------------------------------------------------------
// Launcher
// ---------------------------------------------------------------------------
extern "C" void kernel_launch(void* const* d_in, const int* in_sizes, int n_in,
                              void* d_out, int out_size)
{
    const float* q  = (const float*)d_in[0];
    const float* k  = (const float*)d_in[1];
    const float* v  = (const float*)d_in[2];
    const float* Wq = (const float*)d_in[3];
    const float* bq = (const float*)d_in[4];
    const float* Wk = (const float*)d_in[5];
    const float* bk = (const float*)d_in[6];
    const float* Wv = (const float*)d_in[7];
    const float* bv = (const float*)d_in[8];
    const float* Wo = (const float*)d_in[9];
    const float* bo = (const float*)d_in[10];
    float* out = (float*)d_out;

    __nv_bfloat16 *inh, *inl, *wh, *wl, *ph, *pl, *oh, *ol;
    cudaGetSymbolAddress((void**)&inh, g_inh);
    cudaGetSymbolAddress((void**)&inl, g_inl);
    cudaGetSymbolAddress((void**)&wh,  g_wh);
    cudaGetSymbolAddress((void**)&wl,  g_wl);
    cudaGetSymbolAddress((void**)&ph,  g_ph);
    cudaGetSymbolAddress((void**)&pl,  g_pl);
    cudaGetSymbolAddress((void**)&oh,  g_oh);
    cudaGetSymbolAddress((void**)&ol,  g_ol);

    // one-time splits
    split_kernel<<<2048, 256>>>(q,  inh + 0 * MD_, inl + 0 * MD_, MD_);
    split_kernel<<<2048, 256>>>(k,  inh + 1 * MD_, inl + 1 * MD_, MD_);
    split_kernel<<<2048, 256>>>(v,  inh + 2 * MD_, inl + 2 * MD_, MD_);
    split_kernel<<<512, 256>>>(Wq, wh + 0 * DD_, wl + 0 * DD_, DD_);
    split_kernel<<<512, 256>>>(Wk, wh + 1 * DD_, wl + 1 * DD_, DD_);
    split_kernel<<<512, 256>>>(Wv, wh + 2 * DD_, wl + 2 * DD_, DD_);
    split_kernel<<<512, 256>>>(Wo, wh + 3 * DD_, wl + 3 * DD_, DD_);

    // fused Q/K/V projections (grid.z = 3)
    ProjArgs pa;
    const float* biases[3] = {bq, bk, bv};
    for (int z = 0; z < 3; z++) {
        pa.Ah[z] = inh + (size_t)z * MD_;
        pa.Al[z] = inl + (size_t)z * MD_;
        pa.Wh[z] = wh + (size_t)z * DD_;
        pa.Wl[z] = wl + (size_t)z * DD_;
        pa.bias[z] = biases[z];
        pa.Ch[z] = ph + (size_t)z * MD_;
        pa.Cl[z] = pl + (size_t)z * MD_;
    }
    gemm_proj<<<dim3(D_ / 128, M_ / 128, 3), 256>>>(pa);

    // attention
    cudaFuncSetAttribute(attn_fa, cudaFuncAttributeMaxDynamicSharedMemorySize, ATT_SMEM);
    attn_fa<<<dim3(S_ / 128, B_ * H_), 256, ATT_SMEM>>>(
        ph + 0 * MD_, pl + 0 * MD_,
        ph + 1 * MD_, pl + 1 * MD_,
        ph + 2 * MD_, pl + 2 * MD_,
        oh, ol);

    // output projection
    gemm_out<<<dim3(D_ / 128, M_ / 128), 256>>>(oh, ol, wh + 3 * DD_, wl + 3 * DD_, bo, out);
}